// round 13
// baseline (speedup 1.0000x reference)
#include <cuda_runtime.h>
#include <cuda_bf16.h>

#define B_ 256
#define N_ 1024
#define NT4 4096             // tiles of 32 pairs
#define NPIPE 6
#define STRD (152 * NPIPE)   // 912

#define PRED_OFF (B_*11*N_)                  // 2883584
#define NORM_OFF (PRED_OFF + B_*N_*11*2)     // 8650752

// X tiles: 32 rows x 272B, hi+lo, per pipeline
#define XPIPE 17408          // per-pipeline X block (hi 8704 | lo 8704)
#define OW1H 104448          // W1T hi: 128 rows x 272B
#define OW1L 139264
#define OW2  174080          // 4 x 9216: cn_hi, cn_lo, bn_hi, bn_lo (rows of 144B)
#define OT   210944
#define OB1  211456
#define OB2  211968
#define OLW  212480
#define DSMEM_BYTES 212992

typedef unsigned long long u64;
typedef unsigned int u32;

// ---------------- persistent device scratch ----------------
__device__ __align__(16) float g_e[2][(size_t)B_ * N_ * 64];
__device__ unsigned char g_v[2][B_ * N_];
__device__ __align__(16) __nv_bfloat16 g_W1hi[16384];   // W1T fused [j=128][k=128]
__device__ __align__(16) __nv_bfloat16 g_W1lo[16384];
__device__ __align__(16) __nv_bfloat16 g_W2i[4][4096];  // cn_hi, cn_lo, bn_hi, bn_lo [j=64][k=64]
__device__ float g_B1[128], g_B2[128], g_T[128];

// ---------------- helpers ----------------
__device__ __forceinline__ u32 smem_u32(const void* p) {
    u32 a; asm("{ .reg .u64 t; cvta.to.shared.u64 t, %1; cvt.u32.u64 %0, t; }" : "=r"(a) : "l"(p));
    return a;
}
__device__ __forceinline__ void ldsm4(u32 addr, u32& r0, u32& r1, u32& r2, u32& r3) {
    asm volatile("ldmatrix.sync.aligned.m8n8.x4.shared.b16 {%0,%1,%2,%3}, [%4];"
        : "=r"(r0), "=r"(r1), "=r"(r2), "=r"(r3) : "r"(addr));
}
__device__ __forceinline__ void stsm4(u32 addr, u32 r0, u32 r1, u32 r2, u32 r3) {
    asm volatile("stmatrix.sync.aligned.m8n8.x4.shared.b16 [%0], {%1,%2,%3,%4};"
        :: "r"(addr), "r"(r0), "r"(r1), "r"(r2), "r"(r3) : "memory");
}
__device__ __forceinline__ void mma16816(float* c, const u32* a, u32 b0, u32 b1) {
    asm volatile("mma.sync.aligned.m16n8k16.row.col.f32.bf16.bf16.f32 "
        "{%0,%1,%2,%3}, {%4,%5,%6,%7}, {%8,%9}, {%0,%1,%2,%3};"
        : "+f"(c[0]), "+f"(c[1]), "+f"(c[2]), "+f"(c[3])
        : "r"(a[0]), "r"(a[1]), "r"(a[2]), "r"(a[3]), "r"(b0), "r"(b1));
}
__device__ __forceinline__ u32 pkhi(float a, float b, u32& lopk) {
    __nv_bfloat16 ha = __float2bfloat16(a), hb = __float2bfloat16(b);
    __nv_bfloat16 la = __float2bfloat16(a - __bfloat162float(ha));
    __nv_bfloat16 lb = __float2bfloat16(b - __bfloat162float(hb));
    __nv_bfloat162 H = __halves2bfloat162(ha, hb), L = __halves2bfloat162(la, lb);
    lopk = *(u32*)&L;
    return *(u32*)&H;
}

// ---------------- weight preprocessing ----------------
__global__ void prep_kernel(const float* cnW1, const float* bnW1,
                            const float* cnW2, const float* bnW2,
                            const float* cnb1, const float* bnb1,
                            const float* cnb2, const float* bnb2,
                            const float* lab) {
    int t = threadIdx.x;
    for (int i = t; i < 128 * 128; i += 256) {
        int j = i >> 7, k = i & 127;        // [j][k] transposed image
        float a = (j < 64) ? cnW1[k * 64 + j] : bnW1[k * 64 + (j - 64)];
        __nv_bfloat16 h = __float2bfloat16(a);
        g_W1hi[i] = h;
        g_W1lo[i] = __float2bfloat16(a - __bfloat162float(h));
    }
    for (int i = t; i < 4096; i += 256) {
        int j = i >> 6, k = i & 63;
        float a = cnW2[k * 64 + j];
        __nv_bfloat16 h = __float2bfloat16(a);
        g_W2i[0][i] = h;
        g_W2i[1][i] = __float2bfloat16(a - __bfloat162float(h));
        float bnv = bnW2[k * 64 + j];
        __nv_bfloat16 hb = __float2bfloat16(bnv);
        g_W2i[2][i] = hb;
        g_W2i[3][i] = __float2bfloat16(bnv - __bfloat162float(hb));
    }
    if (t < 64) {
        g_B1[t] = cnb1[t]; g_B1[64 + t] = bnb1[t];
        g_B2[t] = cnb2[t]; g_B2[64 + t] = bnb2[t];
    }
    if (t < 128) {
        int v = t >> 6, j = t & 63;
        float s = 0.f;
        for (int m = 0; m < 64; m++) s += lab[v * 64 + m] * bnW1[(128 + m) * 64 + j];
        g_T[t] = s;
    }
}

// ---------------- stage 0: embedding + fused head ----------------
__global__ void stage0_kernel(const int* __restrict__ x, const float* __restrict__ y,
                              const float* __restrict__ embW, const float* __restrict__ embb,
                              const float* __restrict__ llrW, const float* __restrict__ llrb,
                              float* __restrict__ out) {
    int f = blockIdx.x * blockDim.x + threadIdx.x;
    int pos = f >> 4;
    int c4 = (f & 15) << 2;
    float y0 = y[pos * 2 + 0], y1 = y[pos * 2 + 1];
    float4 w0 = *(const float4*)(embW + c4);
    float4 w1 = *(const float4*)(embW + 64 + c4);
    float4 bb = *(const float4*)(embb + c4);
    float4 e;
    e.x = fmaf(y0, w0.x, fmaf(y1, w1.x, bb.x));
    e.y = fmaf(y0, w0.y, fmaf(y1, w1.y, bb.y));
    e.z = fmaf(y0, w0.z, fmaf(y1, w1.z, bb.z));
    e.w = fmaf(y0, w0.w, fmaf(y1, w1.w, bb.w));
    *(float4*)(&g_e[0][(size_t)pos * 64 + c4]) = e;

    float4 wa = *(const float4*)(llrW + c4 * 2);
    float4 wb = *(const float4*)(llrW + c4 * 2 + 4);
    float l0 = e.x * wa.x + e.y * wa.z + e.z * wb.x + e.w * wb.z;
    float l1 = e.x * wa.y + e.y * wa.w + e.z * wb.y + e.w * wb.w;
    float nr = e.x * e.x + e.y * e.y + e.z * e.z + e.w * e.w;
    #pragma unroll
    for (int o = 8; o >= 1; o >>= 1) {
        l0 += __shfl_xor_sync(0xffffffffu, l0, o);
        l1 += __shfl_xor_sync(0xffffffffu, l1, o);
        nr += __shfl_xor_sync(0xffffffffu, nr, o);
    }
    if ((f & 15) == 0) {
        int v = x[pos];
        g_v[0][pos] = (unsigned char)v;
        l0 += llrb[0]; l1 += llrb[1];
        float m = fmaxf(l0, l1);
        float x0 = expf(l0 - m), x1 = expf(l1 - m);
        float inv = 1.f / (x0 + x1);
        float p0 = x0 * inv, p1 = x1 * inv;
        float pt = v ? p1 : p0;
        float loss = -logf(fminf(fmaxf(pt, 1e-7f), 1.f));
        int b = pos >> 10, p = pos & 1023;
        out[(size_t)b * (11 * N_) + p] = loss;
        float2* pr = (float2*)(out + PRED_OFF + (((size_t)(b * N_ + p)) * 11) * 2);
        *pr = make_float2(p0, p1);
        out[NORM_OFF + (size_t)b * (11 * N_) + p] = sqrtf(nr);
    }
}

// ---------------- main stage kernel: 6 pipelines x 2 warps; warp = 32 rows x one side ----------------
__global__ void __launch_bounds__(384, 1)
stage_kernel(int scope, int src, int s, int dostore,
             const float* __restrict__ llrW, const float* __restrict__ llrb,
             float* __restrict__ out) {
    extern __shared__ char smp[];
    const u32 smb = smem_u32(smp);
    float* sT  = (float*)(smp + OT);
    float* sB1 = (float*)(smp + OB1);
    float* sB2 = (float*)(smp + OB2);
    float* sLW = (float*)(smp + OLW);
    __shared__ unsigned char sVx[NPIPE][2][32], sVe[NPIPE][2][32];

    const int tid = threadIdx.x;

    for (int i = tid; i < 2048; i += 384) {
        int j = i >> 4, c = i & 15;
        *(uint4*)(smp + OW1H + j * 272 + c * 16) = ((const uint4*)g_W1hi)[i];
        *(uint4*)(smp + OW1L + j * 272 + c * 16) = ((const uint4*)g_W1lo)[i];
        int mt = i >> 9, rem = i & 511;
        int j2 = rem >> 3, c2 = rem & 7;
        *(uint4*)(smp + OW2 + mt * 9216 + j2 * 144 + c2 * 16) = ((const uint4*)g_W2i)[i];
    }
    if (tid < 128) { sT[tid] = g_T[tid]; sB1[tid] = g_B1[tid]; sB2[tid] = g_B2[tid]; sLW[tid] = llrW[tid]; }
    __syncthreads();

    const int hsc = scope >> 1;              // half-scope
    const int dst = src ^ 1;
    const int pid = tid / 64;                // pipeline 0..5
    const int lt  = tid & 63;
    const int w = lt >> 5, l = lt & 31;      // warp-in-pipe (= side), lane
    const int side = w;
    const int hbar = 1 + pid;
    const float lb0 = llrb[0], lb1 = llrb[1];

    const u32 xb  = smb + pid * XPIPE;       // X hi (32 x 272B)
    const u32 xbl = xb + 8704;               // X lo
    char* xbp  = smp + pid * XPIPE;
    char* xblp = xbp + 8704;

    // ldmatrix/stmatrix per-thread components (byte offsets)
    const int aoff  = (l & 15) * 272 + (l >> 4) * 16;                           // G1 A
    const int boff1 = ((l & 7) + ((l >> 1) & 8) + side * 64) * 272 + (l & 8) * 2;
    const int aoff2 = (l & 15) * 272 + (side * 64 + ((l >> 4) << 3)) * 2;       // G2 A (own H)
    const int boff2 = ((l & 7) + ((l >> 1) & 8)) * 144 + (l & 8) * 2;
    const u32 w2hiB = smb + OW2 + side * 18432;
    const int stile = l >> 3;
    const int soff  = ((stile & 1) * 8 + (l & 7)) * 272 + (side * 64 + (stile >> 1) * 8) * 2;

    #define HBAR() asm volatile("bar.sync %0, 64;" :: "r"(hbar) : "memory")

    int slot = 0;
    for (int tile = blockIdx.x * NPIPE + pid; tile < NT4; tile += STRD) {
        int b  = tile >> 4;
        int j0 = (tile & 15) << 5;           // 32-pair tile base within batch
        const float* eb = g_e[src] + (size_t)b * (N_ * 64);
        const unsigned char* vb = g_v[src] + b * N_;

        // ---- bits (warp 0 of pipeline) ----
        if (lt < 32) {
            int j = j0 + lt;
            int so = ((j & ~(hsc - 1)) << 1) | (j & (hsc - 1));
            unsigned char vo = vb[so], ve = vb[so + hsc];
            sVx[pid][slot][lt] = (unsigned char)((vo + ve) & 1);
            sVe[pid][slot][lt] = ve;
        }
        // ---- gather: warp w loads source-half w into X cols [w*64, w*64+64) ----
        #pragma unroll
        for (int it = 0; it < 8; it++) {
            int r  = (it << 2) + (l >> 3);   // row 0..31
            int fi = l & 7;                  // 8-dim chunk within the 64-dim half
            int j  = j0 + r;
            int so = ((j & ~(hsc - 1)) << 1) | (j & (hsc - 1));
            const float* p = eb + (size_t)(so + side * hsc) * 64 + (fi << 3);
            float4 v0 = *(const float4*)p;
            float4 v1 = *(const float4*)(p + 4);
            uint4 H, L;
            H.x = pkhi(v0.x, v0.y, L.x); H.y = pkhi(v0.z, v0.w, L.y);
            H.z = pkhi(v1.x, v1.y, L.z); H.w = pkhi(v1.z, v1.w, L.w);
            int ad = r * 272 + (side * 8 + fi) * 16;
            *(uint4*)(xbp + ad)  = H;
            *(uint4*)(xblp + ad) = L;
        }
        HBAR();                              // X ready (both halves)

        // ---- GEMM1: C1[32 x 64(side)] = X[32x128] @ W1T_side^T, 3-term bf16 split ----
        float acc1[2][8][4];
        #pragma unroll
        for (int mt = 0; mt < 2; mt++)
            #pragma unroll
            for (int nt = 0; nt < 8; nt++)
                #pragma unroll
                for (int q = 0; q < 4; q++) acc1[mt][nt][q] = 0.f;

        #pragma unroll
        for (int kc = 0; kc < 8; kc++) {
            int kb = kc * 32;
            u32 ah[2][4], al[2][4];
            #pragma unroll
            for (int mt = 0; mt < 2; mt++) {
                ldsm4(xb + aoff + mt * 4352 + kb,  ah[mt][0], ah[mt][1], ah[mt][2], ah[mt][3]);
                ldsm4(xbl + aoff + mt * 4352 + kb, al[mt][0], al[mt][1], al[mt][2], al[mt][3]);
            }
            #pragma unroll
            for (int np = 0; np < 4; np++) {
                u32 bh[4], bl[4];
                ldsm4(smb + OW1H + boff1 + np * 4352 + kb, bh[0], bh[1], bh[2], bh[3]);
                ldsm4(smb + OW1L + boff1 + np * 4352 + kb, bl[0], bl[1], bl[2], bl[3]);
                #pragma unroll
                for (int mt = 0; mt < 2; mt++) {
                    #pragma unroll
                    for (int hh = 0; hh < 2; hh++) {
                        float* c = acc1[mt][np * 2 + hh];
                        mma16816(c, ah[mt], bh[2 * hh], bh[2 * hh + 1]);
                        mma16816(c, ah[mt], bl[2 * hh], bl[2 * hh + 1]);
                        mma16816(c, al[mt], bh[2 * hh], bh[2 * hh + 1]);
                    }
                }
            }
        }
        HBAR();                              // X free (epi1 may overwrite; next gather safe)

        // ---- epilogue1: h = relu(C1 + b1 + T[vx]) -> H bf16 hi/lo (own col half) ----
        #pragma unroll
        for (int mt = 0; mt < 2; mt++) {
            int rowa = mt * 16 + (l >> 2);
            int rowb = rowa + 8;
            int va = sVx[pid][slot][rowa], vbt = sVx[pid][slot][rowb];
            u32 HI01[8], HI23[8], LO01[8], LO23[8];
            #pragma unroll
            for (int nt = 0; nt < 8; nt++) {
                float* c = acc1[mt][nt];
                int col = side * 64 + nt * 8 + (l & 3) * 2;
                float b0 = sB1[col], b1v = sB1[col + 1];
                float v00 = c[0] + b0, v01 = c[1] + b1v;
                float v10 = c[2] + b0, v11 = c[3] + b1v;
                if (side) {
                    int tcol = col - 64;
                    v00 += sT[va * 64 + tcol];  v01 += sT[va * 64 + tcol + 1];
                    v10 += sT[vbt * 64 + tcol]; v11 += sT[vbt * 64 + tcol + 1];
                }
                v00 = fmaxf(v00, 0.f); v01 = fmaxf(v01, 0.f);
                v10 = fmaxf(v10, 0.f); v11 = fmaxf(v11, 0.f);
                HI01[nt] = pkhi(v00, v01, LO01[nt]);
                HI23[nt] = pkhi(v10, v11, LO23[nt]);
            }
            #pragma unroll
            for (int ntp = 0; ntp < 4; ntp++) {
                u32 sa = soff + mt * 4352 + ntp * 32;
                stsm4(xb + sa,  HI01[2*ntp], HI23[2*ntp], HI01[2*ntp+1], HI23[2*ntp+1]);
                stsm4(xbl + sa, LO01[2*ntp], LO23[2*ntp], LO01[2*ntp+1], LO23[2*ntp+1]);
            }
        }
        __syncwarp();                        // own H visible for own ldsm

        // ---- GEMM2: C2[32 x 64] = H_side @ W2_side (all warp-local) ----
        float acc2[2][8][4];
        #pragma unroll
        for (int mt = 0; mt < 2; mt++)
            #pragma unroll
            for (int nt = 0; nt < 8; nt++)
                #pragma unroll
                for (int q = 0; q < 4; q++) acc2[mt][nt][q] = 0.f;

        #pragma unroll
        for (int kc = 0; kc < 4; kc++) {
            int kb = kc * 32;
            u32 ah[2][4], al[2][4];
            #pragma unroll
            for (int mt = 0; mt < 2; mt++) {
                ldsm4(xb + aoff2 + mt * 4352 + kb,  ah[mt][0], ah[mt][1], ah[mt][2], ah[mt][3]);
                ldsm4(xbl + aoff2 + mt * 4352 + kb, al[mt][0], al[mt][1], al[mt][2], al[mt][3]);
            }
            #pragma unroll
            for (int np = 0; np < 4; np++) {
                u32 bh[4], bl[4];
                ldsm4(w2hiB + boff2 + np * 2304 + kb, bh[0], bh[1], bh[2], bh[3]);
                ldsm4(w2hiB + 9216 + boff2 + np * 2304 + kb, bl[0], bl[1], bl[2], bl[3]);
                #pragma unroll
                for (int mt = 0; mt < 2; mt++) {
                    #pragma unroll
                    for (int hh = 0; hh < 2; hh++) {
                        float* c = acc2[mt][np * 2 + hh];
                        mma16816(c, ah[mt], bh[2 * hh], bh[2 * hh + 1]);
                        mma16816(c, ah[mt], bl[2 * hh], bl[2 * hh + 1]);
                        mma16816(c, al[mt], bh[2 * hh], bh[2 * hh + 1]);
                    }
                }
            }
        }

        // ---- epilogue2: bias + e' store + fused head ----
        #pragma unroll
        for (int mt = 0; mt < 2; mt++) {
            float L0[2] = {0.f, 0.f}, L1[2] = {0.f, 0.f}, NR[2] = {0.f, 0.f};
            int rowa = mt * 16 + (l >> 2);
            int pa = ((j0 + rowa) << 1) | side;
            int pb = ((j0 + rowa + 8) << 1) | side;
            float* ea  = g_e[dst] + ((size_t)b * N_ + pa) * 64;
            float* ebp = g_e[dst] + ((size_t)b * N_ + pb) * 64;
            #pragma unroll
            for (int nt = 0; nt < 8; nt++) {
                float* c = acc2[mt][nt];
                int col = nt * 8 + (l & 3) * 2;
                float b0 = sB2[side * 64 + col], b1v = sB2[side * 64 + col + 1];
                float o00 = c[0] + b0, o01 = c[1] + b1v;
                float o10 = c[2] + b0, o11 = c[3] + b1v;
                if (dostore) {
                    *(float2*)(ea + col)  = make_float2(o00, o01);
                    *(float2*)(ebp + col) = make_float2(o10, o11);
                }
                float w0 = sLW[col * 2], w1 = sLW[col * 2 + 1];
                float w2 = sLW[col * 2 + 2], w3 = sLW[col * 2 + 3];
                L0[0] += o00 * w0 + o01 * w2;
                L1[0] += o00 * w1 + o01 * w3;
                NR[0] += o00 * o00 + o01 * o01;
                L0[1] += o10 * w0 + o11 * w2;
                L1[1] += o10 * w1 + o11 * w3;
                NR[1] += o10 * o10 + o11 * o11;
            }
            #pragma unroll
            for (int off = 2; off >= 1; off >>= 1) {
                #pragma unroll
                for (int hh = 0; hh < 2; hh++) {
                    L0[hh] += __shfl_xor_sync(0xffffffffu, L0[hh], off);
                    L1[hh] += __shfl_xor_sync(0xffffffffu, L1[hh], off);
                    NR[hh] += __shfl_xor_sync(0xffffffffu, NR[hh], off);
                }
            }
            if ((l & 3) == 0) {
                #pragma unroll
                for (int hh = 0; hh < 2; hh++) {
                    int r = mt * 16 + (l >> 2) + hh * 8;
                    int p = ((j0 + r) << 1) | side;
                    unsigned char vp = side ? sVe[pid][slot][r] : sVx[pid][slot][r];
                    if (dostore) g_v[dst][b * N_ + p] = vp;
                    float l0 = L0[hh] + lb0, l1 = L1[hh] + lb1;
                    float mm = fmaxf(l0, l1);
                    float x0 = expf(l0 - mm), x1 = expf(l1 - mm);
                    float inv = 1.f / (x0 + x1);
                    float p0 = x0 * inv, p1 = x1 * inv;
                    float pt = vp ? p1 : p0;
                    float loss = -logf(fminf(fmaxf(pt, 1e-7f), 1.f));
                    out[(size_t)b * (11 * N_) + (size_t)s * N_ + p] = loss;
                    float2* pr = (float2*)(out + PRED_OFF + (((size_t)(b * N_ + p)) * 11 + s) * 2);
                    *pr = make_float2(p0, p1);
                    out[NORM_OFF + (size_t)b * (11 * N_) + (size_t)s * N_ + p] = sqrtf(NR[hh]);
                }
            }
        }
        slot ^= 1;
        // no trailing barrier: all post-B2 smem activity is warp-local (own col half);
        // next tile's gather writes only this warp's col half; X-ready barrier orders cross-warp reads.
    }
    #undef HBAR
}

// ---------------- launch ----------------
extern "C" void kernel_launch(void* const* d_in, const int* in_sizes, int n_in,
                              void* d_out, int out_size) {
    const int*   x    = (const int*)d_in[0];
    const float* y    = (const float*)d_in[1];
    const float* embW = (const float*)d_in[2];
    const float* embb = (const float*)d_in[3];
    const float* lab  = (const float*)d_in[4];
    const float* cnW1 = (const float*)d_in[5];
    const float* cnb1 = (const float*)d_in[6];
    const float* cnW2 = (const float*)d_in[7];
    const float* cnb2 = (const float*)d_in[8];
    const float* bnW1 = (const float*)d_in[9];
    const float* bnb1 = (const float*)d_in[10];
    const float* bnW2 = (const float*)d_in[11];
    const float* bnb2 = (const float*)d_in[12];
    const float* llrW = (const float*)d_in[13];
    const float* llrb = (const float*)d_in[14];
    float* out = (float*)d_out;

    cudaFuncSetAttribute(stage_kernel, cudaFuncAttributeMaxDynamicSharedMemorySize, DSMEM_BYTES);

    prep_kernel<<<1, 256>>>(cnW1, bnW1, cnW2, bnW2, cnb1, bnb1, cnb2, bnb2, lab);
    stage0_kernel<<<(B_ * N_ * 16) / 256, 256>>>(x, y, embW, embb, llrW, llrb, out);
    for (int s = 1; s <= 10; s++) {
        stage_kernel<<<152, 384, DSMEM_BYTES>>>(1 << s, (s - 1) & 1, s, (s < 10) ? 1 : 0, llrW, llrb, out);
    }
}

// round 14
// speedup vs baseline: 1.2656x; 1.2656x over previous
#include <cuda_runtime.h>
#include <cuda_bf16.h>

#define B_ 256
#define N_ 1024
#define NT4 4096             // tiles of 32 pairs (late kernel)
#define NBLK 4096            // 64-position blocks (fused kernel)

#define PRED_OFF (B_*11*N_)                  // 2883584
#define NORM_OFF (PRED_OFF + B_*N_*11*2)     // 8650752

// ---- late-kernel smem layout (R10) ----
#define XPIPE 17408
#define OW1H 69632
#define OW1L 104448
#define OW2  139264
#define OT   176128
#define OB1  176640
#define OB2  177152
#define OLW  177664
#define DSMEM_LATE 178176

// ---- fused-kernel smem layout ----
#define EBLK 18432           // per-pipeline: hi 64x144 | lo 64x144
#define FW1H 73728
#define FW1L 108544
#define FW2  143360
#define FT   180224
#define FB1  180736
#define FB2  181248
#define FLW  181760
#define DSMEM_FUSED 182272

typedef unsigned long long u64;
typedef unsigned int u32;

// ---------------- persistent device scratch ----------------
__device__ __align__(16) float g_e[2][(size_t)B_ * N_ * 64];
__device__ unsigned char g_v[2][B_ * N_];
__device__ __align__(16) __nv_bfloat16 g_ph[(size_t)B_ * N_ * 64];  // stage0 hi plane
__device__ __align__(16) __nv_bfloat16 g_pl[(size_t)B_ * N_ * 64];  // stage0 lo plane
__device__ __align__(16) __nv_bfloat16 g_W1hi[16384];   // W1T fused [j=128][k=128]
__device__ __align__(16) __nv_bfloat16 g_W1lo[16384];
__device__ __align__(16) __nv_bfloat16 g_W2i[4][4096];  // cn_hi, cn_lo, bn_hi, bn_lo [j=64][k=64]
__device__ float g_B1[128], g_B2[128], g_T[128];

// ---------------- helpers ----------------
__device__ __forceinline__ u32 smem_u32(const void* p) {
    u32 a; asm("{ .reg .u64 t; cvta.to.shared.u64 t, %1; cvt.u32.u64 %0, t; }" : "=r"(a) : "l"(p));
    return a;
}
__device__ __forceinline__ void ldsm4(u32 addr, u32& r0, u32& r1, u32& r2, u32& r3) {
    asm volatile("ldmatrix.sync.aligned.m8n8.x4.shared.b16 {%0,%1,%2,%3}, [%4];"
        : "=r"(r0), "=r"(r1), "=r"(r2), "=r"(r3) : "r"(addr));
}
__device__ __forceinline__ void stsm4(u32 addr, u32 r0, u32 r1, u32 r2, u32 r3) {
    asm volatile("stmatrix.sync.aligned.m8n8.x4.shared.b16 [%0], {%1,%2,%3,%4};"
        :: "r"(addr), "r"(r0), "r"(r1), "r"(r2), "r"(r3) : "memory");
}
__device__ __forceinline__ void mma16816(float* c, const u32* a, u32 b0, u32 b1) {
    asm volatile("mma.sync.aligned.m16n8k16.row.col.f32.bf16.bf16.f32 "
        "{%0,%1,%2,%3}, {%4,%5,%6,%7}, {%8,%9}, {%0,%1,%2,%3};"
        : "+f"(c[0]), "+f"(c[1]), "+f"(c[2]), "+f"(c[3])
        : "r"(a[0]), "r"(a[1]), "r"(a[2]), "r"(a[3]), "r"(b0), "r"(b1));
}
__device__ __forceinline__ u32 pkhi(float a, float b, u32& lopk) {
    __nv_bfloat16 ha = __float2bfloat16(a), hb = __float2bfloat16(b);
    __nv_bfloat16 la = __float2bfloat16(a - __bfloat162float(ha));
    __nv_bfloat16 lb = __float2bfloat16(b - __bfloat162float(hb));
    __nv_bfloat162 H = __halves2bfloat162(ha, hb), L = __halves2bfloat162(la, lb);
    lopk = *(u32*)&L;
    return *(u32*)&H;
}

// ---------------- weight preprocessing ----------------
__global__ void prep_kernel(const float* cnW1, const float* bnW1,
                            const float* cnW2, const float* bnW2,
                            const float* cnb1, const float* bnb1,
                            const float* cnb2, const float* bnb2,
                            const float* lab) {
    int t = threadIdx.x;
    for (int i = t; i < 128 * 128; i += 256) {
        int j = i >> 7, k = i & 127;
        float a = (j < 64) ? cnW1[k * 64 + j] : bnW1[k * 64 + (j - 64)];
        __nv_bfloat16 h = __float2bfloat16(a);
        g_W1hi[i] = h;
        g_W1lo[i] = __float2bfloat16(a - __bfloat162float(h));
    }
    for (int i = t; i < 4096; i += 256) {
        int j = i >> 6, k = i & 63;
        float a = cnW2[k * 64 + j];
        __nv_bfloat16 h = __float2bfloat16(a);
        g_W2i[0][i] = h;
        g_W2i[1][i] = __float2bfloat16(a - __bfloat162float(h));
        float bnv = bnW2[k * 64 + j];
        __nv_bfloat16 hb = __float2bfloat16(bnv);
        g_W2i[2][i] = hb;
        g_W2i[3][i] = __float2bfloat16(bnv - __bfloat162float(hb));
    }
    if (t < 64) {
        g_B1[t] = cnb1[t]; g_B1[64 + t] = bnb1[t];
        g_B2[t] = cnb2[t]; g_B2[64 + t] = bnb2[t];
    }
    if (t < 128) {
        int v = t >> 6, j = t & 63;
        float s = 0.f;
        for (int m = 0; m < 64; m++) s += lab[v * 64 + m] * bnW1[(128 + m) * 64 + j];
        g_T[t] = s;
    }
}

// ---------------- stage 0: embedding (hi/lo planes) + fused head ----------------
__global__ void stage0_kernel(const int* __restrict__ x, const float* __restrict__ y,
                              const float* __restrict__ embW, const float* __restrict__ embb,
                              const float* __restrict__ llrW, const float* __restrict__ llrb,
                              float* __restrict__ out) {
    int f = blockIdx.x * blockDim.x + threadIdx.x;
    int pos = f >> 4;
    int c4 = (f & 15) << 2;
    float y0 = y[pos * 2 + 0], y1 = y[pos * 2 + 1];
    float4 w0 = *(const float4*)(embW + c4);
    float4 w1 = *(const float4*)(embW + 64 + c4);
    float4 bb = *(const float4*)(embb + c4);
    float4 e;
    e.x = fmaf(y0, w0.x, fmaf(y1, w1.x, bb.x));
    e.y = fmaf(y0, w0.y, fmaf(y1, w1.y, bb.y));
    e.z = fmaf(y0, w0.z, fmaf(y1, w1.z, bb.z));
    e.w = fmaf(y0, w0.w, fmaf(y1, w1.w, bb.w));
    {
        u32 lo0, lo1;
        u32 h0 = pkhi(e.x, e.y, lo0);
        u32 h1 = pkhi(e.z, e.w, lo1);
        size_t ad = (size_t)pos * 64 + c4;
        *(u32*)(&g_ph[ad])     = h0;
        *(u32*)(&g_ph[ad + 2]) = h1;
        *(u32*)(&g_pl[ad])     = lo0;
        *(u32*)(&g_pl[ad + 2]) = lo1;
    }

    float4 wa = *(const float4*)(llrW + c4 * 2);
    float4 wb = *(const float4*)(llrW + c4 * 2 + 4);
    float l0 = e.x * wa.x + e.y * wa.z + e.z * wb.x + e.w * wb.z;
    float l1 = e.x * wa.y + e.y * wa.w + e.z * wb.y + e.w * wb.w;
    float nr = e.x * e.x + e.y * e.y + e.z * e.z + e.w * e.w;
    #pragma unroll
    for (int o = 8; o >= 1; o >>= 1) {
        l0 += __shfl_xor_sync(0xffffffffu, l0, o);
        l1 += __shfl_xor_sync(0xffffffffu, l1, o);
        nr += __shfl_xor_sync(0xffffffffu, nr, o);
    }
    if ((f & 15) == 0) {
        int v = x[pos];
        g_v[0][pos] = (unsigned char)v;
        l0 += llrb[0]; l1 += llrb[1];
        float m = fmaxf(l0, l1);
        float x0 = expf(l0 - m), x1 = expf(l1 - m);
        float inv = 1.f / (x0 + x1);
        float p0 = x0 * inv, p1 = x1 * inv;
        float pt = v ? p1 : p0;
        float loss = -logf(fminf(fmaxf(pt, 1e-7f), 1.f));
        int b = pos >> 10, p = pos & 1023;
        out[(size_t)b * (11 * N_) + p] = loss;
        float2* pr = (float2*)(out + PRED_OFF + (((size_t)(b * N_ + p)) * 11) * 2);
        *pr = make_float2(p0, p1);
        out[NORM_OFF + (size_t)b * (11 * N_) + p] = sqrtf(nr);
    }
}

// ---------------- fused stages 1..6: 4 pipelines, e-block resident in smem ----------------
__global__ void __launch_bounds__(512, 1)
fused16_kernel(const float* __restrict__ llrW, const float* __restrict__ llrb,
               float* __restrict__ out) {
    extern __shared__ char smp[];
    const u32 smb = smem_u32(smp);
    float* sT  = (float*)(smp + FT);
    float* sB1 = (float*)(smp + FB1);
    float* sB2 = (float*)(smp + FB2);
    float* sLW = (float*)(smp + FLW);
    __shared__ unsigned char sV[4][2][64];

    const int tid = threadIdx.x;
    {   // stage weights (same images as late kernel, fused offsets)
        #pragma unroll
        for (int it = 0; it < 4; it++) {
            int i = tid + it * 512;
            int j = i >> 4, c = i & 15;
            *(uint4*)(smp + FW1H + j * 272 + c * 16) = ((const uint4*)g_W1hi)[i];
            *(uint4*)(smp + FW1L + j * 272 + c * 16) = ((const uint4*)g_W1lo)[i];
            int mt = i >> 9, rem = i & 511;
            int j2 = rem >> 3, c2 = rem & 7;
            *(uint4*)(smp + FW2 + mt * 9216 + j2 * 144 + c2 * 16) = ((const uint4*)g_W2i)[i];
        }
        if (tid < 128) { sT[tid] = g_T[tid]; sB1[tid] = g_B1[tid]; sB2[tid] = g_B2[tid]; sLW[tid] = llrW[tid]; }
    }
    __syncthreads();

    const int pid = tid >> 7;                // pipeline 0..3
    const int lt  = tid & 127;
    const int w = lt >> 5, l = lt & 31;
    const int r0 = (w & 1) * 16;             // pair-row base
    const int side = w >> 1;                 // output/col side
    const int hbar = 1 + pid;
    const float lb0 = llrb[0], lb1 = llrb[1];

    char* ebh_p = smp + pid * EBLK;
    char* ebl_p = ebh_p + 9216;
    const u32 ebh = smb + pid * EBLK;
    const u32 ebl = ebh + 9216;

    const int boff1 = ((l & 7) + ((l >> 1) & 8) + side * 64) * 272 + (l & 8) * 2;
    const int boff2 = ((l & 7) + ((l >> 1) & 8)) * 144 + (l & 8) * 2;
    const u32 w2hiB = smb + FW2 + side * 18432;

    #define HBAR() asm volatile("bar.sync %0, 128;" :: "r"(hbar) : "memory")

    for (int B0 = blockIdx.x * 4 + pid; B0 < NBLK; B0 += 608) {
        const int b = B0 >> 4;
        const int pbase = (B0 & 15) << 6;    // position base within batch
        const size_t gpos = (size_t)B0 << 6; // global position base

        // ---- entry: load e planes + bits ----
        #pragma unroll
        for (int it = 0; it < 8; it++) {
            int c = lt + (it << 7);          // 0..1023
            int pl = c >> 9, rem = c & 511;
            int r = rem >> 3, ck = rem & 7;
            const __nv_bfloat16* src = (pl ? g_pl : g_ph) + (gpos + r) * 64 + (ck << 3);
            *(uint4*)((pl ? ebl_p : ebh_p) + r * 144 + ck * 16) = *(const uint4*)src;
        }
        if (lt < 64) sV[pid][1][lt] = g_v[0][gpos + lt];
        HBAR();

        #pragma unroll 1
        for (int s = 1; s <= 6; s++) {
            const int half = 1 << (s - 1), hm = half - 1;
            const int par = s & 1;

            // ---- GEMM1: A from e-block with butterfly row addressing ----
            const int ra = r0 + (l & 15);
            const int sro = ((ra & ~hm) << 1) | (ra & hm);
            float acc1[8][4];
            #pragma unroll
            for (int nt = 0; nt < 8; nt++)
                #pragma unroll
                for (int q = 0; q < 4; q++) acc1[nt][q] = 0.f;

            #pragma unroll
            for (int kc = 0; kc < 8; kc++) {
                int sr = sro + ((kc >= 4) ? half : 0);
                u32 aaddr = (u32)(sr * 144 + ((kc & 3) << 5) + ((l >> 4) << 4));
                u32 ah[4], al[4];
                ldsm4(ebh + aaddr, ah[0], ah[1], ah[2], ah[3]);
                ldsm4(ebl + aaddr, al[0], al[1], al[2], al[3]);
                #pragma unroll
                for (int np = 0; np < 4; np++) {
                    u32 bh[4], bl[4];
                    ldsm4(smb + FW1H + boff1 + np * 4352 + kc * 32, bh[0], bh[1], bh[2], bh[3]);
                    ldsm4(smb + FW1L + boff1 + np * 4352 + kc * 32, bl[0], bl[1], bl[2], bl[3]);
                    #pragma unroll
                    for (int hh = 0; hh < 2; hh++) {
                        float* c = acc1[np * 2 + hh];
                        mma16816(c, ah, bh[2 * hh], bh[2 * hh + 1]);
                        mma16816(c, ah, bl[2 * hh], bl[2 * hh + 1]);
                        mma16816(c, al, bh[2 * hh], bh[2 * hh + 1]);
                    }
                }
            }
            HBAR();                          // all e-block reads done

            // ---- epilogue1 in registers -> GEMM2 A-fragments ----
            u32 a2h[4][4], a2l[4][4];
            int ja = r0 + (l >> 2), jb = ja + 8;
            int soa = ((ja & ~hm) << 1) | (ja & hm);
            int sob = ((jb & ~hm) << 1) | (jb & hm);
            {
                int va  = (sV[pid][par][soa] + sV[pid][par][soa + half]) & 1;
                int vbt = (sV[pid][par][sob] + sV[pid][par][sob + half]) & 1;
                #pragma unroll
                for (int nt = 0; nt < 8; nt++) {
                    float* c = acc1[nt];
                    int col = side * 64 + nt * 8 + (l & 3) * 2;
                    float b0 = sB1[col], b1v = sB1[col + 1];
                    float v00 = c[0] + b0, v01 = c[1] + b1v;
                    float v10 = c[2] + b0, v11 = c[3] + b1v;
                    if (side) {
                        int tcol = col - 64;
                        v00 += sT[va * 64 + tcol];  v01 += sT[va * 64 + tcol + 1];
                        v10 += sT[vbt * 64 + tcol]; v11 += sT[vbt * 64 + tcol + 1];
                    }
                    v00 = fmaxf(v00, 0.f); v01 = fmaxf(v01, 0.f);
                    v10 = fmaxf(v10, 0.f); v11 = fmaxf(v11, 0.f);
                    int kc2 = nt >> 1, qq = (nt & 1) * 2;
                    a2h[kc2][qq]     = pkhi(v00, v01, a2l[kc2][qq]);
                    a2h[kc2][qq + 1] = pkhi(v10, v11, a2l[kc2][qq + 1]);
                }
            }

            // ---- GEMM2 (A in registers) ----
            float acc2[8][4];
            #pragma unroll
            for (int nt = 0; nt < 8; nt++)
                #pragma unroll
                for (int q = 0; q < 4; q++) acc2[nt][q] = 0.f;

            #pragma unroll
            for (int kc = 0; kc < 4; kc++) {
                #pragma unroll
                for (int np = 0; np < 4; np++) {
                    u32 bh[4], bl[4];
                    ldsm4(w2hiB + boff2 + np * 2304 + kc * 32, bh[0], bh[1], bh[2], bh[3]);
                    ldsm4(w2hiB + 9216 + boff2 + np * 2304 + kc * 32, bl[0], bl[1], bl[2], bl[3]);
                    #pragma unroll
                    for (int hh = 0; hh < 2; hh++) {
                        float* c = acc2[np * 2 + hh];
                        mma16816(c, a2h[kc], bh[2 * hh], bh[2 * hh + 1]);
                        mma16816(c, a2h[kc], bl[2 * hh], bl[2 * hh + 1]);
                        mma16816(c, a2l[kc], bh[2 * hh], bh[2 * hh + 1]);
                    }
                }
            }

            // ---- epilogue2: e' writes + head ----
            {
                int pra = (ja << 1) | side;  // local output positions
                int prb = (jb << 1) | side;
                float L0[2] = {0.f, 0.f}, L1[2] = {0.f, 0.f}, NR[2] = {0.f, 0.f};
                float* ea  = g_e[0] + ((size_t)b * N_ + pbase + pra) * 64;
                float* ebp = g_e[0] + ((size_t)b * N_ + pbase + prb) * 64;
                #pragma unroll
                for (int nt = 0; nt < 8; nt++) {
                    float* c = acc2[nt];
                    int col = nt * 8 + (l & 3) * 2;
                    float b0 = sB2[side * 64 + col], b1v = sB2[side * 64 + col + 1];
                    float o00 = c[0] + b0, o01 = c[1] + b1v;
                    float o10 = c[2] + b0, o11 = c[3] + b1v;
                    if (s < 6) {
                        u32 lo0, lo1;
                        u32 hi0 = pkhi(o00, o01, lo0);
                        u32 hi1 = pkhi(o10, o11, lo1);
                        *(u32*)(ebh_p + pra * 144 + col * 2) = hi0;
                        *(u32*)(ebl_p + pra * 144 + col * 2) = lo0;
                        *(u32*)(ebh_p + prb * 144 + col * 2) = hi1;
                        *(u32*)(ebl_p + prb * 144 + col * 2) = lo1;
                    } else {
                        *(float2*)(ea + col)  = make_float2(o00, o01);
                        *(float2*)(ebp + col) = make_float2(o10, o11);
                    }
                    float w0 = sLW[col * 2], w1 = sLW[col * 2 + 1];
                    float w2 = sLW[col * 2 + 2], w3 = sLW[col * 2 + 3];
                    L0[0] += o00 * w0 + o01 * w2;
                    L1[0] += o00 * w1 + o01 * w3;
                    NR[0] += o00 * o00 + o01 * o01;
                    L0[1] += o10 * w0 + o11 * w2;
                    L1[1] += o10 * w1 + o11 * w3;
                    NR[1] += o10 * o10 + o11 * o11;
                }
                #pragma unroll
                for (int off = 2; off >= 1; off >>= 1) {
                    #pragma unroll
                    for (int hh = 0; hh < 2; hh++) {
                        L0[hh] += __shfl_xor_sync(0xffffffffu, L0[hh], off);
                        L1[hh] += __shfl_xor_sync(0xffffffffu, L1[hh], off);
                        NR[hh] += __shfl_xor_sync(0xffffffffu, NR[hh], off);
                    }
                }
                if ((l & 3) == 0) {
                    #pragma unroll
                    for (int hh = 0; hh < 2; hh++) {
                        int jj = hh ? jb : ja;
                        int so = hh ? sob : soa;
                        int pr = (jj << 1) | side;
                        unsigned char vxb = (unsigned char)((sV[pid][par][so] + sV[pid][par][so + half]) & 1);
                        unsigned char veb = sV[pid][par][so + half];
                        unsigned char vp = side ? veb : vxb;
                        if (s < 6) sV[pid][par ^ 1][pr] = vp;
                        else       g_v[0][(size_t)b * N_ + pbase + pr] = vp;
                        int p = pbase + pr;
                        float l0 = L0[hh] + lb0, l1 = L1[hh] + lb1;
                        float mm = fmaxf(l0, l1);
                        float x0 = expf(l0 - mm), x1 = expf(l1 - mm);
                        float inv = 1.f / (x0 + x1);
                        float p0 = x0 * inv, p1 = x1 * inv;
                        float pt = vp ? p1 : p0;
                        float loss = -logf(fminf(fmaxf(pt, 1e-7f), 1.f));
                        out[(size_t)b * (11 * N_) + (size_t)s * N_ + p] = loss;
                        float2* pr2 = (float2*)(out + PRED_OFF + (((size_t)(b * N_ + p)) * 11 + s) * 2);
                        *pr2 = make_float2(p0, p1);
                        out[NORM_OFF + (size_t)b * (11 * N_) + (size_t)s * N_ + p] = sqrtf(NR[hh]);
                    }
                }
            }
            HBAR();                          // e'/v' visible before next stage reads
        }
    }
    #undef HBAR
}

// ---------------- late stages 7..10 (R10 kernel + dostore) ----------------
__global__ void __launch_bounds__(512, 1)
stage_kernel(int scope, int src, int s, int dostore,
             const float* __restrict__ llrW, const float* __restrict__ llrb,
             float* __restrict__ out) {
    extern __shared__ char smp[];
    const u32 smb = smem_u32(smp);
    float* sT  = (float*)(smp + OT);
    float* sB1 = (float*)(smp + OB1);
    float* sB2 = (float*)(smp + OB2);
    float* sLW = (float*)(smp + OLW);
    __shared__ unsigned char sVx[4][32], sVe[4][32];

    const int tid = threadIdx.x;

    {
        #pragma unroll
        for (int it = 0; it < 4; it++) {
            int i = tid + it * 512;
            int j = i >> 4, c = i & 15;
            *(uint4*)(smp + OW1H + j * 272 + c * 16) = ((const uint4*)g_W1hi)[i];
            *(uint4*)(smp + OW1L + j * 272 + c * 16) = ((const uint4*)g_W1lo)[i];
            int mt = i >> 9, rem = i & 511;
            int j2 = rem >> 3, c2 = rem & 7;
            *(uint4*)(smp + OW2 + mt * 9216 + j2 * 144 + c2 * 16) = ((const uint4*)g_W2i)[i];
        }
        if (tid < 128) { sT[tid] = g_T[tid]; sB1[tid] = g_B1[tid]; sB2[tid] = g_B2[tid]; sLW[tid] = llrW[tid]; }
    }
    __syncthreads();

    const int hsc = scope >> 1;
    const int dst = src ^ 1;
    const int pid = tid >> 7;
    const int lt  = tid & 127;
    const int w = lt >> 5, l = lt & 31;
    const int hbar = 1 + pid;

    const int n0 = w * 32;
    const int side1 = w >> 1;
    const int wm2 = w & 1, side2 = w >> 1;
    const int r0b = wm2 * 16;
    const float lb0 = llrb[0], lb1 = llrb[1];

    const u32 xb  = smb + pid * XPIPE;
    const u32 xbl = xb + 8704;
    char* xbp  = smp + pid * XPIPE;
    char* xblp = xbp + 8704;

    const int aoff  = (l & 15) * 272 + (l >> 4) * 16;
    const int boff1 = ((l & 7) + ((l >> 1) & 8) + n0) * 272 + (l & 8) * 2;
    const int aoff2 = (r0b + (l & 15)) * 272 + (side2 * 64 + ((l >> 4) << 3)) * 2;
    const int boff2 = ((l & 7) + ((l >> 1) & 8)) * 144 + (l & 8) * 2;
    const u32 w2hiB = smb + OW2 + side2 * 18432;
    const int stile = l >> 3;
    const int soff = ((stile & 1) * 8 + (l & 7)) * 272 + (n0 + (stile >> 1) * 8) * 2;

    #define HBAR() asm volatile("bar.sync %0, 128;" :: "r"(hbar) : "memory")

    for (int tile = blockIdx.x * 4 + pid; tile < NT4; tile += 608) {
        int b  = tile >> 4;
        int j0 = (tile & 15) << 5;
        const float* eb = g_e[src] + (size_t)b * (N_ * 64);
        const unsigned char* vb = g_v[src] + b * N_;

        if (lt < 32) {
            int j = j0 + lt;
            int so = ((j & ~(hsc - 1)) << 1) | (j & (hsc - 1));
            unsigned char vo = vb[so], ve = vb[so + hsc];
            sVx[pid][lt] = (unsigned char)((vo + ve) & 1);
            sVe[pid][lt] = ve;
        }
        #pragma unroll
        for (int it = 0; it < 4; it++) {
            int c  = lt + (it << 7);
            int r  = c >> 4;
            int f8 = c & 15;
            int hs = f8 >> 3;
            int j  = j0 + r;
            int so = ((j & ~(hsc - 1)) << 1) | (j & (hsc - 1));
            const float* p = eb + (size_t)(so + hs * hsc) * 64 + ((f8 & 7) << 3);
            float4 v0 = *(const float4*)p;
            float4 v1 = *(const float4*)(p + 4);
            uint4 H, L;
            H.x = pkhi(v0.x, v0.y, L.x); H.y = pkhi(v0.z, v0.w, L.y);
            H.z = pkhi(v1.x, v1.y, L.z); H.w = pkhi(v1.z, v1.w, L.w);
            int ad = r * 272 + f8 * 16;
            *(uint4*)(xbp + ad)  = H;
            *(uint4*)(xblp + ad) = L;
        }
        HBAR();

        float acc[2][4][4];
        #pragma unroll
        for (int mt = 0; mt < 2; mt++)
            #pragma unroll
            for (int nt = 0; nt < 4; nt++)
                #pragma unroll
                for (int q = 0; q < 4; q++) acc[mt][nt][q] = 0.f;

        #pragma unroll
        for (int kc = 0; kc < 8; kc++) {
            int kb = kc * 32;
            u32 ah[2][4], al[2][4];
            #pragma unroll
            for (int mt = 0; mt < 2; mt++) {
                ldsm4(xb + aoff + mt * 16 * 272 + kb,  ah[mt][0], ah[mt][1], ah[mt][2], ah[mt][3]);
                ldsm4(xbl + aoff + mt * 16 * 272 + kb, al[mt][0], al[mt][1], al[mt][2], al[mt][3]);
            }
            #pragma unroll
            for (int np = 0; np < 2; np++) {
                u32 bh[4], bl[4];
                ldsm4(smb + OW1H + boff1 + np * 16 * 272 + kb, bh[0], bh[1], bh[2], bh[3]);
                ldsm4(smb + OW1L + boff1 + np * 16 * 272 + kb, bl[0], bl[1], bl[2], bl[3]);
                #pragma unroll
                for (int mt = 0; mt < 2; mt++) {
                    #pragma unroll
                    for (int hh = 0; hh < 2; hh++) {
                        float* c = acc[mt][np * 2 + hh];
                        mma16816(c, ah[mt], bh[2 * hh], bh[2 * hh + 1]);
                        mma16816(c, ah[mt], bl[2 * hh], bl[2 * hh + 1]);
                        mma16816(c, al[mt], bh[2 * hh], bh[2 * hh + 1]);
                    }
                }
            }
        }
        HBAR();

        #pragma unroll
        for (int mt = 0; mt < 2; mt++) {
            int rowa = mt * 16 + (l >> 2);
            int rowb = rowa + 8;
            int va = sVx[pid][rowa], vbt = sVx[pid][rowb];
            u32 HI01[4], HI23[4], LO01[4], LO23[4];
            #pragma unroll
            for (int nt = 0; nt < 4; nt++) {
                float* c = acc[mt][nt];
                int col = n0 + nt * 8 + (l & 3) * 2;
                float b0 = sB1[col], b1v = sB1[col + 1];
                float v00 = c[0] + b0, v01 = c[1] + b1v;
                float v10 = c[2] + b0, v11 = c[3] + b1v;
                if (side1) {
                    int tcol = col - 64;
                    v00 += sT[va * 64 + tcol];  v01 += sT[va * 64 + tcol + 1];
                    v10 += sT[vbt * 64 + tcol]; v11 += sT[vbt * 64 + tcol + 1];
                }
                v00 = fmaxf(v00, 0.f); v01 = fmaxf(v01, 0.f);
                v10 = fmaxf(v10, 0.f); v11 = fmaxf(v11, 0.f);
                HI01[nt] = pkhi(v00, v01, LO01[nt]);
                HI23[nt] = pkhi(v10, v11, LO23[nt]);
            }
            #pragma unroll
            for (int ntp = 0; ntp < 2; ntp++) {
                u32 sa = soff + mt * 16 * 272 + ntp * 32;
                stsm4(xb + sa,  HI01[2*ntp], HI23[2*ntp], HI01[2*ntp+1], HI23[2*ntp+1]);
                stsm4(xbl + sa, LO01[2*ntp], LO23[2*ntp], LO01[2*ntp+1], LO23[2*ntp+1]);
            }
        }
        HBAR();

        float acc2[8][4];
        #pragma unroll
        for (int nt = 0; nt < 8; nt++)
            #pragma unroll
            for (int q = 0; q < 4; q++) acc2[nt][q] = 0.f;

        #pragma unroll
        for (int kc = 0; kc < 4; kc++) {
            int kb = kc * 32;
            u32 ah[4], al[4];
            ldsm4(xb + aoff2 + kb,  ah[0], ah[1], ah[2], ah[3]);
            ldsm4(xbl + aoff2 + kb, al[0], al[1], al[2], al[3]);
            #pragma unroll
            for (int np = 0; np < 4; np++) {
                u32 bh[4], bl[4];
                ldsm4(w2hiB + boff2 + np * 16 * 144 + kb, bh[0], bh[1], bh[2], bh[3]);
                ldsm4(w2hiB + 9216 + boff2 + np * 16 * 144 + kb, bl[0], bl[1], bl[2], bl[3]);
                #pragma unroll
                for (int hh = 0; hh < 2; hh++) {
                    float* c = acc2[np * 2 + hh];
                    mma16816(c, ah, bh[2 * hh], bh[2 * hh + 1]);
                    mma16816(c, ah, bl[2 * hh], bl[2 * hh + 1]);
                    mma16816(c, al, bh[2 * hh], bh[2 * hh + 1]);
                }
            }
        }

        {
            float L0[2] = {0.f, 0.f}, L1[2] = {0.f, 0.f}, NR[2] = {0.f, 0.f};
            int rowa = r0b + (l >> 2);
            int pa = ((j0 + rowa) << 1) | side2;
            int pb = ((j0 + rowa + 8) << 1) | side2;
            float* ea  = g_e[dst] + ((size_t)b * N_ + pa) * 64;
            float* ebp = g_e[dst] + ((size_t)b * N_ + pb) * 64;
            #pragma unroll
            for (int nt = 0; nt < 8; nt++) {
                float* c = acc2[nt];
                int col = nt * 8 + (l & 3) * 2;
                float b0 = sB2[side2 * 64 + col], b1v = sB2[side2 * 64 + col + 1];
                float o00 = c[0] + b0, o01 = c[1] + b1v;
                float o10 = c[2] + b0, o11 = c[3] + b1v;
                if (dostore) {
                    *(float2*)(ea + col)  = make_float2(o00, o01);
                    *(float2*)(ebp + col) = make_float2(o10, o11);
                }
                float w0 = sLW[col * 2], w1 = sLW[col * 2 + 1];
                float w2 = sLW[col * 2 + 2], w3 = sLW[col * 2 + 3];
                L0[0] += o00 * w0 + o01 * w2;
                L1[0] += o00 * w1 + o01 * w3;
                NR[0] += o00 * o00 + o01 * o01;
                L0[1] += o10 * w0 + o11 * w2;
                L1[1] += o10 * w1 + o11 * w3;
                NR[1] += o10 * o10 + o11 * o11;
            }
            #pragma unroll
            for (int off = 2; off >= 1; off >>= 1) {
                #pragma unroll
                for (int hh = 0; hh < 2; hh++) {
                    L0[hh] += __shfl_xor_sync(0xffffffffu, L0[hh], off);
                    L1[hh] += __shfl_xor_sync(0xffffffffu, L1[hh], off);
                    NR[hh] += __shfl_xor_sync(0xffffffffu, NR[hh], off);
                }
            }
            if ((l & 3) == 0) {
                #pragma unroll
                for (int hh = 0; hh < 2; hh++) {
                    int r = r0b + (l >> 2) + hh * 8;
                    int p = ((j0 + r) << 1) | side2;
                    unsigned char vp = side2 ? sVe[pid][r] : sVx[pid][r];
                    if (dostore) g_v[dst][b * N_ + p] = vp;
                    float l0 = L0[hh] + lb0, l1 = L1[hh] + lb1;
                    float mm = fmaxf(l0, l1);
                    float x0 = expf(l0 - mm), x1 = expf(l1 - mm);
                    float inv = 1.f / (x0 + x1);
                    float p0 = x0 * inv, p1 = x1 * inv;
                    float pt = vp ? p1 : p0;
                    float loss = -logf(fminf(fmaxf(pt, 1e-7f), 1.f));
                    out[(size_t)b * (11 * N_) + (size_t)s * N_ + p] = loss;
                    float2* pr = (float2*)(out + PRED_OFF + (((size_t)(b * N_ + p)) * 11 + s) * 2);
                    *pr = make_float2(p0, p1);
                    out[NORM_OFF + (size_t)b * (11 * N_) + (size_t)s * N_ + p] = sqrtf(NR[hh]);
                }
            }
        }
        HBAR();
    }
    #undef HBAR
}

// ---------------- launch ----------------
extern "C" void kernel_launch(void* const* d_in, const int* in_sizes, int n_in,
                              void* d_out, int out_size) {
    const int*   x    = (const int*)d_in[0];
    const float* y    = (const float*)d_in[1];
    const float* embW = (const float*)d_in[2];
    const float* embb = (const float*)d_in[3];
    const float* lab  = (const float*)d_in[4];
    const float* cnW1 = (const float*)d_in[5];
    const float* cnb1 = (const float*)d_in[6];
    const float* cnW2 = (const float*)d_in[7];
    const float* cnb2 = (const float*)d_in[8];
    const float* bnW1 = (const float*)d_in[9];
    const float* bnb1 = (const float*)d_in[10];
    const float* bnW2 = (const float*)d_in[11];
    const float* bnb2 = (const float*)d_in[12];
    const float* llrW = (const float*)d_in[13];
    const float* llrb = (const float*)d_in[14];
    float* out = (float*)d_out;

    cudaFuncSetAttribute(fused16_kernel, cudaFuncAttributeMaxDynamicSharedMemorySize, DSMEM_FUSED);
    cudaFuncSetAttribute(stage_kernel, cudaFuncAttributeMaxDynamicSharedMemorySize, DSMEM_LATE);

    prep_kernel<<<1, 256>>>(cnW1, bnW1, cnW2, bnW2, cnb1, bnb1, cnb2, bnb2, lab);
    stage0_kernel<<<(B_ * N_ * 16) / 256, 256>>>(x, y, embW, embb, llrW, llrb, out);
    fused16_kernel<<<152, 512, DSMEM_FUSED>>>(llrW, llrb, out);
    for (int s = 7; s <= 10; s++) {
        stage_kernel<<<152, 512, DSMEM_LATE>>>(1 << s, (s - 1) & 1, s, (s < 10) ? 1 : 0, llrW, llrb, out);
    }
}

// round 16
// speedup vs baseline: 1.3886x; 1.0972x over previous
#include <cuda_runtime.h>
#include <cuda_bf16.h>

#define B_ 256
#define N_ 1024
#define NBLK 4096            // 64-position blocks

#define PRED_OFF (B_*11*N_)                  // 2883584
#define NORM_OFF (PRED_OFF + B_*N_*11*2)     // 8650752

// ---- fused-kernel smem layout ----
#define EBLK 18432           // per-pipeline: hi 64x144 | lo 64x144
#define FW1H 73728
#define FW1L 108544
#define FW2  143360
#define FT   180224
#define FB1  180736
#define FB2  181248
#define FLW  181760
#define DSMEM_FUSED 182272

typedef unsigned long long u64;
typedef unsigned int u32;

// ---------------- persistent device scratch ----------------
__device__ __align__(16) float g_e[2][(size_t)B_ * N_ * 64];
__device__ unsigned char g_v[2][B_ * N_];
__device__ __align__(16) __nv_bfloat16 g_ph[(size_t)B_ * N_ * 64];  // stage0 hi plane
__device__ __align__(16) __nv_bfloat16 g_pl[(size_t)B_ * N_ * 64];  // stage0 lo plane
__device__ __align__(16) __nv_bfloat16 g_W1hi[16384];   // W1T fused [j=128][k=128]
__device__ __align__(16) __nv_bfloat16 g_W1lo[16384];
__device__ __align__(16) __nv_bfloat16 g_W2i[4][4096];  // cn_hi, cn_lo, bn_hi, bn_lo [j=64][k=64]
__device__ float g_B1[128], g_B2[128], g_T[128];

// ---------------- helpers ----------------
__device__ __forceinline__ u32 smem_u32(const void* p) {
    u32 a; asm("{ .reg .u64 t; cvta.to.shared.u64 t, %1; cvt.u32.u64 %0, t; }" : "=r"(a) : "l"(p));
    return a;
}
__device__ __forceinline__ void ldsm4(u32 addr, u32& r0, u32& r1, u32& r2, u32& r3) {
    asm volatile("ldmatrix.sync.aligned.m8n8.x4.shared.b16 {%0,%1,%2,%3}, [%4];"
        : "=r"(r0), "=r"(r1), "=r"(r2), "=r"(r3) : "r"(addr));
}
__device__ __forceinline__ void mma16816(float* c, const u32* a, u32 b0, u32 b1) {
    asm volatile("mma.sync.aligned.m16n8k16.row.col.f32.bf16.bf16.f32 "
        "{%0,%1,%2,%3}, {%4,%5,%6,%7}, {%8,%9}, {%0,%1,%2,%3};"
        : "+f"(c[0]), "+f"(c[1]), "+f"(c[2]), "+f"(c[3])
        : "r"(a[0]), "r"(a[1]), "r"(a[2]), "r"(a[3]), "r"(b0), "r"(b1));
}
__device__ __forceinline__ u32 pkhi(float a, float b, u32& lopk) {
    __nv_bfloat16 ha = __float2bfloat16(a), hb = __float2bfloat16(b);
    __nv_bfloat16 la = __float2bfloat16(a - __bfloat162float(ha));
    __nv_bfloat16 lb = __float2bfloat16(b - __bfloat162float(hb));
    __nv_bfloat162 H = __halves2bfloat162(ha, hb), L = __halves2bfloat162(la, lb);
    lopk = *(u32*)&L;
    return *(u32*)&H;
}

// ---------------- weight preprocessing ----------------
__global__ void prep_kernel(const float* cnW1, const float* bnW1,
                            const float* cnW2, const float* bnW2,
                            const float* cnb1, const float* bnb1,
                            const float* cnb2, const float* bnb2,
                            const float* lab) {
    int t = threadIdx.x;
    for (int i = t; i < 128 * 128; i += 256) {
        int j = i >> 7, k = i & 127;
        float a = (j < 64) ? cnW1[k * 64 + j] : bnW1[k * 64 + (j - 64)];
        __nv_bfloat16 h = __float2bfloat16(a);
        g_W1hi[i] = h;
        g_W1lo[i] = __float2bfloat16(a - __bfloat162float(h));
    }
    for (int i = t; i < 4096; i += 256) {
        int j = i >> 6, k = i & 63;
        float a = cnW2[k * 64 + j];
        __nv_bfloat16 h = __float2bfloat16(a);
        g_W2i[0][i] = h;
        g_W2i[1][i] = __float2bfloat16(a - __bfloat162float(h));
        float bnv = bnW2[k * 64 + j];
        __nv_bfloat16 hb = __float2bfloat16(bnv);
        g_W2i[2][i] = hb;
        g_W2i[3][i] = __float2bfloat16(bnv - __bfloat162float(hb));
    }
    if (t < 64) {
        g_B1[t] = cnb1[t]; g_B1[64 + t] = bnb1[t];
        g_B2[t] = cnb2[t]; g_B2[64 + t] = bnb2[t];
    }
    if (t < 128) {
        int v = t >> 6, j = t & 63;
        float s = 0.f;
        for (int m = 0; m < 64; m++) s += lab[v * 64 + m] * bnW1[(128 + m) * 64 + j];
        g_T[t] = s;
    }
}

// ---------------- stage 0: embedding (hi/lo planes) + fused head ----------------
__global__ void stage0_kernel(const int* __restrict__ x, const float* __restrict__ y,
                              const float* __restrict__ embW, const float* __restrict__ embb,
                              const float* __restrict__ llrW, const float* __restrict__ llrb,
                              float* __restrict__ out) {
    int f = blockIdx.x * blockDim.x + threadIdx.x;
    int pos = f >> 4;
    int c4 = (f & 15) << 2;
    float y0 = y[pos * 2 + 0], y1 = y[pos * 2 + 1];
    float4 w0 = *(const float4*)(embW + c4);
    float4 w1 = *(const float4*)(embW + 64 + c4);
    float4 bb = *(const float4*)(embb + c4);
    float4 e;
    e.x = fmaf(y0, w0.x, fmaf(y1, w1.x, bb.x));
    e.y = fmaf(y0, w0.y, fmaf(y1, w1.y, bb.y));
    e.z = fmaf(y0, w0.z, fmaf(y1, w1.z, bb.z));
    e.w = fmaf(y0, w0.w, fmaf(y1, w1.w, bb.w));
    {
        u32 lo0, lo1;
        u32 h0 = pkhi(e.x, e.y, lo0);
        u32 h1 = pkhi(e.z, e.w, lo1);
        size_t ad = (size_t)pos * 64 + c4;
        *(u32*)(&g_ph[ad])     = h0;
        *(u32*)(&g_ph[ad + 2]) = h1;
        *(u32*)(&g_pl[ad])     = lo0;
        *(u32*)(&g_pl[ad + 2]) = lo1;
    }

    float4 wa = *(const float4*)(llrW + c4 * 2);
    float4 wb = *(const float4*)(llrW + c4 * 2 + 4);
    float l0 = e.x * wa.x + e.y * wa.z + e.z * wb.x + e.w * wb.z;
    float l1 = e.x * wa.y + e.y * wa.w + e.z * wb.y + e.w * wb.w;
    float nr = e.x * e.x + e.y * e.y + e.z * e.z + e.w * e.w;
    #pragma unroll
    for (int o = 8; o >= 1; o >>= 1) {
        l0 += __shfl_xor_sync(0xffffffffu, l0, o);
        l1 += __shfl_xor_sync(0xffffffffu, l1, o);
        nr += __shfl_xor_sync(0xffffffffu, nr, o);
    }
    if ((f & 15) == 0) {
        int v = x[pos];
        g_v[0][pos] = (unsigned char)v;
        l0 += llrb[0]; l1 += llrb[1];
        float m = fmaxf(l0, l1);
        float x0 = expf(l0 - m), x1 = expf(l1 - m);
        float inv = 1.f / (x0 + x1);
        float p0 = x0 * inv, p1 = x1 * inv;
        float pt = v ? p1 : p0;
        float loss = -logf(fminf(fmaxf(pt, 1e-7f), 1.f));
        int b = pos >> 10, p = pos & 1023;
        out[(size_t)b * (11 * N_) + p] = loss;
        float2* pr = (float2*)(out + PRED_OFF + (((size_t)(b * N_ + p)) * 11) * 2);
        *pr = make_float2(p0, p1);
        out[NORM_OFF + (size_t)b * (11 * N_) + p] = sqrtf(nr);
    }
}

// ---------------- fused stages 1..6 ----------------
__global__ void __launch_bounds__(512, 1)
fused16_kernel(const float* __restrict__ llrW, const float* __restrict__ llrb,
               float* __restrict__ out) {
    extern __shared__ char smp[];
    const u32 smb = smem_u32(smp);
    float* sT  = (float*)(smp + FT);
    float* sB1 = (float*)(smp + FB1);
    float* sB2 = (float*)(smp + FB2);
    float* sLW = (float*)(smp + FLW);
    __shared__ unsigned char sV[4][2][64];

    const int tid = threadIdx.x;
    {
        #pragma unroll
        for (int it = 0; it < 4; it++) {
            int i = tid + it * 512;
            int j = i >> 4, c = i & 15;
            *(uint4*)(smp + FW1H + j * 272 + c * 16) = ((const uint4*)g_W1hi)[i];
            *(uint4*)(smp + FW1L + j * 272 + c * 16) = ((const uint4*)g_W1lo)[i];
            int mt = i >> 9, rem = i & 511;
            int j2 = rem >> 3, c2 = rem & 7;
            *(uint4*)(smp + FW2 + mt * 9216 + j2 * 144 + c2 * 16) = ((const uint4*)g_W2i)[i];
        }
        if (tid < 128) { sT[tid] = g_T[tid]; sB1[tid] = g_B1[tid]; sB2[tid] = g_B2[tid]; sLW[tid] = llrW[tid]; }
    }
    __syncthreads();

    const int pid = tid >> 7;
    const int lt  = tid & 127;
    const int w = lt >> 5, l = lt & 31;
    const int r0 = (w & 1) * 16;
    const int side = w >> 1;
    const int hbar = 1 + pid;
    const float lb0 = llrb[0], lb1 = llrb[1];

    char* ebh_p = smp + pid * EBLK;
    char* ebl_p = ebh_p + 9216;
    const u32 ebh = smb + pid * EBLK;
    const u32 ebl = ebh + 9216;

    const int boff1 = ((l & 7) + ((l >> 1) & 8) + side * 64) * 272 + (l & 8) * 2;
    const int boff2 = ((l & 7) + ((l >> 1) & 8)) * 144 + (l & 8) * 2;
    const u32 w2hiB = smb + FW2 + side * 18432;

    #define HBAR() asm volatile("bar.sync %0, 128;" :: "r"(hbar) : "memory")

    for (int B0 = blockIdx.x * 4 + pid; B0 < NBLK; B0 += 608) {
        const int b = B0 >> 4;
        const int pbase = (B0 & 15) << 6;
        const size_t gpos = (size_t)B0 << 6;

        #pragma unroll
        for (int it = 0; it < 8; it++) {
            int c = lt + (it << 7);
            int pl = c >> 9, rem = c & 511;
            int r = rem >> 3, ck = rem & 7;
            const __nv_bfloat16* src = (pl ? g_pl : g_ph) + (gpos + r) * 64 + (ck << 3);
            *(uint4*)((pl ? ebl_p : ebh_p) + r * 144 + ck * 16) = *(const uint4*)src;
        }
        if (lt < 64) sV[pid][1][lt] = g_v[0][gpos + lt];
        HBAR();

        #pragma unroll 1
        for (int s = 1; s <= 6; s++) {
            const int half = 1 << (s - 1), hm = half - 1;
            const int par = s & 1;

            const int ra = r0 + (l & 15);
            const int sro = ((ra & ~hm) << 1) | (ra & hm);
            float acc1[8][4];
            #pragma unroll
            for (int nt = 0; nt < 8; nt++)
                #pragma unroll
                for (int q = 0; q < 4; q++) acc1[nt][q] = 0.f;

            #pragma unroll
            for (int kc = 0; kc < 8; kc++) {
                int sr = sro + ((kc >= 4) ? half : 0);
                u32 aaddr = (u32)(sr * 144 + ((kc & 3) << 5) + ((l >> 4) << 4));
                u32 ah[4], al[4];
                ldsm4(ebh + aaddr, ah[0], ah[1], ah[2], ah[3]);
                ldsm4(ebl + aaddr, al[0], al[1], al[2], al[3]);
                #pragma unroll
                for (int np = 0; np < 4; np++) {
                    u32 bh[4], bl[4];
                    ldsm4(smb + FW1H + boff1 + np * 4352 + kc * 32, bh[0], bh[1], bh[2], bh[3]);
                    ldsm4(smb + FW1L + boff1 + np * 4352 + kc * 32, bl[0], bl[1], bl[2], bl[3]);
                    #pragma unroll
                    for (int hh = 0; hh < 2; hh++) {
                        float* c = acc1[np * 2 + hh];
                        mma16816(c, ah, bh[2 * hh], bh[2 * hh + 1]);
                        mma16816(c, ah, bl[2 * hh], bl[2 * hh + 1]);
                        mma16816(c, al, bh[2 * hh], bh[2 * hh + 1]);
                    }
                }
            }
            HBAR();

            u32 a2h[4][4], a2l[4][4];
            int ja = r0 + (l >> 2), jb = ja + 8;
            int soa = ((ja & ~hm) << 1) | (ja & hm);
            int sob = ((jb & ~hm) << 1) | (jb & hm);
            {
                int va  = (sV[pid][par][soa] + sV[pid][par][soa + half]) & 1;
                int vbt = (sV[pid][par][sob] + sV[pid][par][sob + half]) & 1;
                #pragma unroll
                for (int nt = 0; nt < 8; nt++) {
                    float* c = acc1[nt];
                    int col = side * 64 + nt * 8 + (l & 3) * 2;
                    float b0 = sB1[col], b1v = sB1[col + 1];
                    float v00 = c[0] + b0, v01 = c[1] + b1v;
                    float v10 = c[2] + b0, v11 = c[3] + b1v;
                    if (side) {
                        int tcol = col - 64;
                        v00 += sT[va * 64 + tcol];  v01 += sT[va * 64 + tcol + 1];
                        v10 += sT[vbt * 64 + tcol]; v11 += sT[vbt * 64 + tcol + 1];
                    }
                    v00 = fmaxf(v00, 0.f); v01 = fmaxf(v01, 0.f);
                    v10 = fmaxf(v10, 0.f); v11 = fmaxf(v11, 0.f);
                    int kc2 = nt >> 1, qq = (nt & 1) * 2;
                    a2h[kc2][qq]     = pkhi(v00, v01, a2l[kc2][qq]);
                    a2h[kc2][qq + 1] = pkhi(v10, v11, a2l[kc2][qq + 1]);
                }
            }

            float acc2[8][4];
            #pragma unroll
            for (int nt = 0; nt < 8; nt++)
                #pragma unroll
                for (int q = 0; q < 4; q++) acc2[nt][q] = 0.f;

            #pragma unroll
            for (int kc = 0; kc < 4; kc++) {
                #pragma unroll
                for (int np = 0; np < 4; np++) {
                    u32 bh[4], bl[4];
                    ldsm4(w2hiB + boff2 + np * 2304 + kc * 32, bh[0], bh[1], bh[2], bh[3]);
                    ldsm4(w2hiB + 9216 + boff2 + np * 2304 + kc * 32, bl[0], bl[1], bl[2], bl[3]);
                    #pragma unroll
                    for (int hh = 0; hh < 2; hh++) {
                        float* c = acc2[np * 2 + hh];
                        mma16816(c, a2h[kc], bh[2 * hh], bh[2 * hh + 1]);
                        mma16816(c, a2h[kc], bl[2 * hh], bl[2 * hh + 1]);
                        mma16816(c, a2l[kc], bh[2 * hh], bh[2 * hh + 1]);
                    }
                }
            }

            {
                int pra = (ja << 1) | side;
                int prb = (jb << 1) | side;
                float L0[2] = {0.f, 0.f}, L1[2] = {0.f, 0.f}, NR[2] = {0.f, 0.f};
                float* ea  = g_e[0] + ((size_t)b * N_ + pbase + pra) * 64;
                float* ebp = g_e[0] + ((size_t)b * N_ + pbase + prb) * 64;
                #pragma unroll
                for (int nt = 0; nt < 8; nt++) {
                    float* c = acc2[nt];
                    int col = nt * 8 + (l & 3) * 2;
                    float b0 = sB2[side * 64 + col], b1v = sB2[side * 64 + col + 1];
                    float o00 = c[0] + b0, o01 = c[1] + b1v;
                    float o10 = c[2] + b0, o11 = c[3] + b1v;
                    if (s < 6) {
                        u32 lo0, lo1;
                        u32 hi0 = pkhi(o00, o01, lo0);
                        u32 hi1 = pkhi(o10, o11, lo1);
                        *(u32*)(ebh_p + pra * 144 + col * 2) = hi0;
                        *(u32*)(ebl_p + pra * 144 + col * 2) = lo0;
                        *(u32*)(ebh_p + prb * 144 + col * 2) = hi1;
                        *(u32*)(ebl_p + prb * 144 + col * 2) = lo1;
                    } else {
                        *(float2*)(ea + col)  = make_float2(o00, o01);
                        *(float2*)(ebp + col) = make_float2(o10, o11);
                    }
                    float w0 = sLW[col * 2], w1 = sLW[col * 2 + 1];
                    float w2 = sLW[col * 2 + 2], w3 = sLW[col * 2 + 3];
                    L0[0] += o00 * w0 + o01 * w2;
                    L1[0] += o00 * w1 + o01 * w3;
                    NR[0] += o00 * o00 + o01 * o01;
                    L0[1] += o10 * w0 + o11 * w2;
                    L1[1] += o10 * w1 + o11 * w3;
                    NR[1] += o10 * o10 + o11 * o11;
                }
                #pragma unroll
                for (int off = 2; off >= 1; off >>= 1) {
                    #pragma unroll
                    for (int hh = 0; hh < 2; hh++) {
                        L0[hh] += __shfl_xor_sync(0xffffffffu, L0[hh], off);
                        L1[hh] += __shfl_xor_sync(0xffffffffu, L1[hh], off);
                        NR[hh] += __shfl_xor_sync(0xffffffffu, NR[hh], off);
                    }
                }
                if ((l & 3) == 0) {
                    #pragma unroll
                    for (int hh = 0; hh < 2; hh++) {
                        int jj = hh ? jb : ja;
                        int so = hh ? sob : soa;
                        int pr = (jj << 1) | side;
                        unsigned char vxb = (unsigned char)((sV[pid][par][so] + sV[pid][par][so + half]) & 1);
                        unsigned char veb = sV[pid][par][so + half];
                        unsigned char vp = side ? veb : vxb;
                        if (s < 6) sV[pid][par ^ 1][pr] = vp;
                        else       g_v[0][(size_t)b * N_ + pbase + pr] = vp;
                        int p = pbase + pr;
                        float l0 = L0[hh] + lb0, l1 = L1[hh] + lb1;
                        float mm = fmaxf(l0, l1);
                        float x0 = expf(l0 - mm), x1 = expf(l1 - mm);
                        float inv = 1.f / (x0 + x1);
                        float p0 = x0 * inv, p1 = x1 * inv;
                        float pt = vp ? p1 : p0;
                        float loss = -logf(fminf(fmaxf(pt, 1e-7f), 1.f));
                        out[(size_t)b * (11 * N_) + (size_t)s * N_ + p] = loss;
                        float2* pr2 = (float2*)(out + PRED_OFF + (((size_t)(b * N_ + p)) * 11 + s) * 2);
                        *pr2 = make_float2(p0, p1);
                        out[NORM_OFF + (size_t)b * (11 * N_) + (size_t)s * N_ + p] = sqrtf(NR[hh]);
                    }
                }
            }
            HBAR();
        }
    }
    #undef HBAR
}

// ---------------- fused late pair (sA, sA+1), sA in {7, 9} ----------------
__global__ void __launch_bounds__(512, 1)
fusedlate_kernel(int sA, int src, int dostore,
                 const float* __restrict__ llrW, const float* __restrict__ llrb,
                 float* __restrict__ out) {
    extern __shared__ char smp[];
    const u32 smb = smem_u32(smp);
    float* sT  = (float*)(smp + FT);
    float* sB1 = (float*)(smp + FB1);
    float* sB2 = (float*)(smp + FB2);
    float* sLW = (float*)(smp + FLW);
    __shared__ unsigned char sV[4][2][64];

    const int tid = threadIdx.x;
    {
        #pragma unroll
        for (int it = 0; it < 4; it++) {
            int i = tid + it * 512;
            int j = i >> 4, c = i & 15;
            *(uint4*)(smp + FW1H + j * 272 + c * 16) = ((const uint4*)g_W1hi)[i];
            *(uint4*)(smp + FW1L + j * 272 + c * 16) = ((const uint4*)g_W1lo)[i];
            int mt = i >> 9, rem = i & 511;
            int j2 = rem >> 3, c2 = rem & 7;
            *(uint4*)(smp + FW2 + mt * 9216 + j2 * 144 + c2 * 16) = ((const uint4*)g_W2i)[i];
        }
        if (tid < 128) { sT[tid] = g_T[tid]; sB1[tid] = g_B1[tid]; sB2[tid] = g_B2[tid]; sLW[tid] = llrW[tid]; }
    }
    __syncthreads();

    const int pid = tid >> 7;
    const int lt  = tid & 127;
    const int w = lt >> 5, l = lt & 31;
    const int r0 = (w & 1) * 16;
    const int side = w >> 1;
    const int hbar = 1 + pid;
    const int dst = src ^ 1;
    const int halfA = 1 << (sA - 1);
    const float lb0 = llrb[0], lb1 = llrb[1];

    char* ebh_p = smp + pid * EBLK;
    char* ebl_p = ebh_p + 9216;
    const u32 ebh = smb + pid * EBLK;
    const u32 ebl = ebh + 9216;

    const int boff1 = ((l & 7) + ((l >> 1) & 8) + side * 64) * 272 + (l & 8) * 2;
    const int boff2 = ((l & 7) + ((l >> 1) & 8)) * 144 + (l & 8) * 2;
    const u32 w2hiB = smb + FW2 + side * 18432;

    #define HBAR() asm volatile("bar.sync %0, 128;" :: "r"(hbar) : "memory")
    // local row ri (0..63) -> global source row
    #define GIMAP(RI) (hbase + ((RI) >> 5) * (halfA << 1) + ((((RI) >> 4) & 1)) * halfA + (m0 >> 1) + ((RI) & 15))

    for (int T = blockIdx.x * 4 + pid; T < NBLK; T += 608) {
        const int b = T >> 4;
        const int tau = T & 15;
        const int h = tau >> (sA - 5);
        const int hbase = h << (sA + 1);
        const int m0 = (tau & ((1 << (sA - 5)) - 1)) << 5;
        const float* ebg = g_e[src] + (size_t)b * (N_ * 64);
        const unsigned char* vbg = g_v[src] + (size_t)b * N_;

        // ---- entry: gather fp32 rows -> hi/lo e-block, plus bits ----
        #pragma unroll
        for (int it = 0; it < 4; it++) {
            int c = lt + (it << 7);          // 0..511
            int r = c >> 3, f8 = c & 7;
            int gi = GIMAP(r);
            const float* p = ebg + (size_t)gi * 64 + (f8 << 3);
            float4 v0 = *(const float4*)p;
            float4 v1 = *(const float4*)(p + 4);
            uint4 H, L;
            H.x = pkhi(v0.x, v0.y, L.x); H.y = pkhi(v0.z, v0.w, L.y);
            H.z = pkhi(v1.x, v1.y, L.z); H.w = pkhi(v1.z, v1.w, L.w);
            *(uint4*)(ebh_p + r * 144 + f8 * 16) = H;
            *(uint4*)(ebl_p + r * 144 + f8 * 16) = L;
        }
        if (lt < 64) sV[pid][0][lt] = vbg[GIMAP(lt)];
        HBAR();

        #pragma unroll
        for (int it2 = 0; it2 < 2; it2++) {
            const int half = 16 << it2, hm = half - 1;
            const int s = sA + it2;

            const int ra = r0 + (l & 15);
            const int sro = ((ra & ~hm) << 1) | (ra & hm);
            float acc1[8][4];
            #pragma unroll
            for (int nt = 0; nt < 8; nt++)
                #pragma unroll
                for (int q = 0; q < 4; q++) acc1[nt][q] = 0.f;

            #pragma unroll
            for (int kc = 0; kc < 8; kc++) {
                int sr = sro + ((kc >= 4) ? half : 0);
                u32 aaddr = (u32)(sr * 144 + ((kc & 3) << 5) + ((l >> 4) << 4));
                u32 ah[4], al[4];
                ldsm4(ebh + aaddr, ah[0], ah[1], ah[2], ah[3]);
                ldsm4(ebl + aaddr, al[0], al[1], al[2], al[3]);
                #pragma unroll
                for (int np = 0; np < 4; np++) {
                    u32 bh[4], bl[4];
                    ldsm4(smb + FW1H + boff1 + np * 4352 + kc * 32, bh[0], bh[1], bh[2], bh[3]);
                    ldsm4(smb + FW1L + boff1 + np * 4352 + kc * 32, bl[0], bl[1], bl[2], bl[3]);
                    #pragma unroll
                    for (int hh = 0; hh < 2; hh++) {
                        float* c = acc1[np * 2 + hh];
                        mma16816(c, ah, bh[2 * hh], bh[2 * hh + 1]);
                        mma16816(c, ah, bl[2 * hh], bl[2 * hh + 1]);
                        mma16816(c, al, bh[2 * hh], bh[2 * hh + 1]);
                    }
                }
            }
            HBAR();

            u32 a2h[4][4], a2l[4][4];
            int ja = r0 + (l >> 2), jb = ja + 8;
            int soa = ((ja & ~hm) << 1) | (ja & hm);
            int sob = ((jb & ~hm) << 1) | (jb & hm);
            {
                int va  = (sV[pid][it2][soa] + sV[pid][it2][soa + half]) & 1;
                int vbt = (sV[pid][it2][sob] + sV[pid][it2][sob + half]) & 1;
                #pragma unroll
                for (int nt = 0; nt < 8; nt++) {
                    float* c = acc1[nt];
                    int col = side * 64 + nt * 8 + (l & 3) * 2;
                    float b0 = sB1[col], b1v = sB1[col + 1];
                    float v00 = c[0] + b0, v01 = c[1] + b1v;
                    float v10 = c[2] + b0, v11 = c[3] + b1v;
                    if (side) {
                        int tcol = col - 64;
                        v00 += sT[va * 64 + tcol];  v01 += sT[va * 64 + tcol + 1];
                        v10 += sT[vbt * 64 + tcol]; v11 += sT[vbt * 64 + tcol + 1];
                    }
                    v00 = fmaxf(v00, 0.f); v01 = fmaxf(v01, 0.f);
                    v10 = fmaxf(v10, 0.f); v11 = fmaxf(v11, 0.f);
                    int kc2 = nt >> 1, qq = (nt & 1) * 2;
                    a2h[kc2][qq]     = pkhi(v00, v01, a2l[kc2][qq]);
                    a2h[kc2][qq + 1] = pkhi(v10, v11, a2l[kc2][qq + 1]);
                }
            }

            float acc2[8][4];
            #pragma unroll
            for (int nt = 0; nt < 8; nt++)
                #pragma unroll
                for (int q = 0; q < 4; q++) acc2[nt][q] = 0.f;

            #pragma unroll
            for (int kc = 0; kc < 4; kc++) {
                #pragma unroll
                for (int np = 0; np < 4; np++) {
                    u32 bh[4], bl[4];
                    ldsm4(w2hiB + boff2 + np * 2304 + kc * 32, bh[0], bh[1], bh[2], bh[3]);
                    ldsm4(w2hiB + 9216 + boff2 + np * 2304 + kc * 32, bl[0], bl[1], bl[2], bl[3]);
                    #pragma unroll
                    for (int hh = 0; hh < 2; hh++) {
                        float* c = acc2[np * 2 + hh];
                        mma16816(c, a2h[kc], bh[2 * hh], bh[2 * hh + 1]);
                        mma16816(c, a2h[kc], bl[2 * hh], bl[2 * hh + 1]);
                        mma16816(c, a2l[kc], bh[2 * hh], bh[2 * hh + 1]);
                    }
                }
            }

            {
                int pra = (ja << 1) | side;
                int prb = (jb << 1) | side;
                int gpa, gpb;
                if (it2 == 0) {
                    gpa = hbase + ((pra >> 5) << sA) + m0 + (pra & 31);
                    gpb = hbase + ((prb >> 5) << sA) + m0 + (prb & 31);
                } else {
                    gpa = hbase + (m0 << 1) + pra;
                    gpb = hbase + (m0 << 1) + prb;
                }
                float L0[2] = {0.f, 0.f}, L1[2] = {0.f, 0.f}, NR[2] = {0.f, 0.f};
                float* ea  = g_e[dst] + ((size_t)b * N_ + gpa) * 64;
                float* ebp = g_e[dst] + ((size_t)b * N_ + gpb) * 64;
                #pragma unroll
                for (int nt = 0; nt < 8; nt++) {
                    float* c = acc2[nt];
                    int col = nt * 8 + (l & 3) * 2;
                    float b0 = sB2[side * 64 + col], b1v = sB2[side * 64 + col + 1];
                    float o00 = c[0] + b0, o01 = c[1] + b1v;
                    float o10 = c[2] + b0, o11 = c[3] + b1v;
                    if (it2 == 0) {
                        u32 lo0, lo1;
                        u32 hi0 = pkhi(o00, o01, lo0);
                        u32 hi1 = pkhi(o10, o11, lo1);
                        *(u32*)(ebh_p + pra * 144 + col * 2) = hi0;
                        *(u32*)(ebl_p + pra * 144 + col * 2) = lo0;
                        *(u32*)(ebh_p + prb * 144 + col * 2) = hi1;
                        *(u32*)(ebl_p + prb * 144 + col * 2) = lo1;
                    } else if (dostore) {
                        *(float2*)(ea + col)  = make_float2(o00, o01);
                        *(float2*)(ebp + col) = make_float2(o10, o11);
                    }
                    float w0 = sLW[col * 2], w1 = sLW[col * 2 + 1];
                    float w2 = sLW[col * 2 + 2], w3 = sLW[col * 2 + 3];
                    L0[0] += o00 * w0 + o01 * w2;
                    L1[0] += o00 * w1 + o01 * w3;
                    NR[0] += o00 * o00 + o01 * o01;
                    L0[1] += o10 * w0 + o11 * w2;
                    L1[1] += o10 * w1 + o11 * w3;
                    NR[1] += o10 * o10 + o11 * o11;
                }
                #pragma unroll
                for (int off = 2; off >= 1; off >>= 1) {
                    #pragma unroll
                    for (int hh = 0; hh < 2; hh++) {
                        L0[hh] += __shfl_xor_sync(0xffffffffu, L0[hh], off);
                        L1[hh] += __shfl_xor_sync(0xffffffffu, L1[hh], off);
                        NR[hh] += __shfl_xor_sync(0xffffffffu, NR[hh], off);
                    }
                }
                if ((l & 3) == 0) {
                    #pragma unroll
                    for (int hh = 0; hh < 2; hh++) {
                        int jj = hh ? jb : ja;
                        int so = hh ? sob : soa;
                        int pr = (jj << 1) | side;
                        int gp = hh ? gpb : gpa;
                        unsigned char vxb = (unsigned char)((sV[pid][it2][so] + sV[pid][it2][so + half]) & 1);
                        unsigned char veb = sV[pid][it2][so + half];
                        unsigned char vp = side ? veb : vxb;
                        if (it2 == 0)      sV[pid][1][pr] = vp;
                        else if (dostore)  g_v[dst][(size_t)b * N_ + gp] = vp;
                        float l0 = L0[hh] + lb0, l1 = L1[hh] + lb1;
                        float mm = fmaxf(l0, l1);
                        float x0 = expf(l0 - mm), x1 = expf(l1 - mm);
                        float inv = 1.f / (x0 + x1);
                        float p0 = x0 * inv, p1 = x1 * inv;
                        float pt = vp ? p1 : p0;
                        float loss = -logf(fminf(fmaxf(pt, 1e-7f), 1.f));
                        out[(size_t)b * (11 * N_) + (size_t)s * N_ + gp] = loss;
                        float2* pr2 = (float2*)(out + PRED_OFF + (((size_t)(b * N_ + gp)) * 11 + s) * 2);
                        *pr2 = make_float2(p0, p1);
                        out[NORM_OFF + (size_t)b * (11 * N_) + (size_t)s * N_ + gp] = sqrtf(NR[hh]);
                    }
                }
            }
            HBAR();
        }
    }
    #undef HBAR
    #undef GIMAP
}

// ---------------- launch ----------------
extern "C" void kernel_launch(void* const* d_in, const int* in_sizes, int n_in,
                              void* d_out, int out_size) {
    const int*   x    = (const int*)d_in[0];
    const float* y    = (const float*)d_in[1];
    const float* embW = (const float*)d_in[2];
    const float* embb = (const float*)d_in[3];
    const float* lab  = (const float*)d_in[4];
    const float* cnW1 = (const float*)d_in[5];
    const float* cnb1 = (const float*)d_in[6];
    const float* cnW2 = (const float*)d_in[7];
    const float* cnb2 = (const float*)d_in[8];
    const float* bnW1 = (const float*)d_in[9];
    const float* bnb1 = (const float*)d_in[10];
    const float* bnW2 = (const float*)d_in[11];
    const float* bnb2 = (const float*)d_in[12];
    const float* llrW = (const float*)d_in[13];
    const float* llrb = (const float*)d_in[14];
    float* out = (float*)d_out;

    cudaFuncSetAttribute(fused16_kernel, cudaFuncAttributeMaxDynamicSharedMemorySize, DSMEM_FUSED);
    cudaFuncSetAttribute(fusedlate_kernel, cudaFuncAttributeMaxDynamicSharedMemorySize, DSMEM_FUSED);

    prep_kernel<<<1, 256>>>(cnW1, bnW1, cnW2, bnW2, cnb1, bnb1, cnb2, bnb2, lab);
    stage0_kernel<<<(B_ * N_ * 16) / 256, 256>>>(x, y, embW, embb, llrW, llrb, out);
    fused16_kernel<<<152, 512, DSMEM_FUSED>>>(llrW, llrb, out);
    fusedlate_kernel<<<152, 512, DSMEM_FUSED>>>(7, 0, 1, llrW, llrb, out);   // stages 7+8
    fusedlate_kernel<<<152, 512, DSMEM_FUSED>>>(9, 1, 0, llrW, llrb, out);   // stages 9+10
}

// round 17
// speedup vs baseline: 1.4159x; 1.0197x over previous
#include <cuda_runtime.h>
#include <cuda_bf16.h>

#define B_ 256
#define N_ 1024
#define NBLK 4096            // 64-position blocks

#define PRED_OFF (B_*11*N_)                  // 2883584
#define NORM_OFF (PRED_OFF + B_*N_*11*2)     // 8650752

// ---- fused-kernel smem layout ----
#define EBLK 18432           // per-pipeline: hi 64x144 | lo 64x144
#define FW1H 73728
#define FW1L 108544
#define FW2  143360
#define FT   180224
#define FB1  180736
#define FB2  181248
#define FLW  181760
#define FEW  182272          // embW (128 f) + embb (64 f)
#define DSMEM_FUSED 183296

typedef unsigned long long u64;
typedef unsigned int u32;

// ---------------- persistent device scratch ----------------
__device__ __align__(16) __nv_bfloat16 g_pln_h[2][(size_t)B_ * N_ * 64];  // hi planes (ping/pong)
__device__ __align__(16) __nv_bfloat16 g_pln_l[2][(size_t)B_ * N_ * 64];  // lo planes
__device__ unsigned char g_v[2][B_ * N_];
__device__ __align__(16) __nv_bfloat16 g_W1hi[16384];   // W1T fused [j=128][k=128]
__device__ __align__(16) __nv_bfloat16 g_W1lo[16384];
__device__ __align__(16) __nv_bfloat16 g_W2i[4][4096];  // cn_hi, cn_lo, bn_hi, bn_lo [j=64][k=64]
__device__ float g_B1[128], g_B2[128], g_T[128];

// ---------------- helpers ----------------
__device__ __forceinline__ u32 smem_u32(const void* p) {
    u32 a; asm("{ .reg .u64 t; cvta.to.shared.u64 t, %1; cvt.u32.u64 %0, t; }" : "=r"(a) : "l"(p));
    return a;
}
__device__ __forceinline__ void ldsm4(u32 addr, u32& r0, u32& r1, u32& r2, u32& r3) {
    asm volatile("ldmatrix.sync.aligned.m8n8.x4.shared.b16 {%0,%1,%2,%3}, [%4];"
        : "=r"(r0), "=r"(r1), "=r"(r2), "=r"(r3) : "r"(addr));
}
__device__ __forceinline__ void mma16816(float* c, const u32* a, u32 b0, u32 b1) {
    asm volatile("mma.sync.aligned.m16n8k16.row.col.f32.bf16.bf16.f32 "
        "{%0,%1,%2,%3}, {%4,%5,%6,%7}, {%8,%9}, {%0,%1,%2,%3};"
        : "+f"(c[0]), "+f"(c[1]), "+f"(c[2]), "+f"(c[3])
        : "r"(a[0]), "r"(a[1]), "r"(a[2]), "r"(a[3]), "r"(b0), "r"(b1));
}
__device__ __forceinline__ u32 pkhi(float a, float b, u32& lopk) {
    __nv_bfloat16 ha = __float2bfloat16(a), hb = __float2bfloat16(b);
    __nv_bfloat16 la = __float2bfloat16(a - __bfloat162float(ha));
    __nv_bfloat16 lb = __float2bfloat16(b - __bfloat162float(hb));
    __nv_bfloat162 H = __halves2bfloat162(ha, hb), L = __halves2bfloat162(la, lb);
    lopk = *(u32*)&L;
    return *(u32*)&H;
}

// ---------------- weight preprocessing ----------------
__global__ void prep_kernel(const float* cnW1, const float* bnW1,
                            const float* cnW2, const float* bnW2,
                            const float* cnb1, const float* bnb1,
                            const float* cnb2, const float* bnb2,
                            const float* lab) {
    int t = threadIdx.x;
    for (int i = t; i < 128 * 128; i += 256) {
        int j = i >> 7, k = i & 127;
        float a = (j < 64) ? cnW1[k * 64 + j] : bnW1[k * 64 + (j - 64)];
        __nv_bfloat16 h = __float2bfloat16(a);
        g_W1hi[i] = h;
        g_W1lo[i] = __float2bfloat16(a - __bfloat162float(h));
    }
    for (int i = t; i < 4096; i += 256) {
        int j = i >> 6, k = i & 63;
        float a = cnW2[k * 64 + j];
        __nv_bfloat16 h = __float2bfloat16(a);
        g_W2i[0][i] = h;
        g_W2i[1][i] = __float2bfloat16(a - __bfloat162float(h));
        float bnv = bnW2[k * 64 + j];
        __nv_bfloat16 hb = __float2bfloat16(bnv);
        g_W2i[2][i] = hb;
        g_W2i[3][i] = __float2bfloat16(bnv - __bfloat162float(hb));
    }
    if (t < 64) {
        g_B1[t] = cnb1[t]; g_B1[64 + t] = bnb1[t];
        g_B2[t] = cnb2[t]; g_B2[64 + t] = bnb2[t];
    }
    if (t < 128) {
        int v = t >> 6, j = t & 63;
        float s = 0.f;
        for (int m = 0; m < 64; m++) s += lab[v * 64 + m] * bnW1[(128 + m) * 64 + j];
        g_T[t] = s;
    }
}

// ---------------- fused stages 0..6 (stage0 inline at entry) ----------------
__global__ void __launch_bounds__(512, 1)
fused16_kernel(const int* __restrict__ xg, const float* __restrict__ yg,
               const float* __restrict__ embW, const float* __restrict__ embb,
               const float* __restrict__ llrW, const float* __restrict__ llrb,
               float* __restrict__ out) {
    extern __shared__ char smp[];
    const u32 smb = smem_u32(smp);
    float* sT  = (float*)(smp + FT);
    float* sB1 = (float*)(smp + FB1);
    float* sB2 = (float*)(smp + FB2);
    float* sLW = (float*)(smp + FLW);
    float* sEW = (float*)(smp + FEW);        // 128: embW, then 64: embb
    __shared__ unsigned char sV[4][2][64];

    const int tid = threadIdx.x;
    {
        #pragma unroll
        for (int it = 0; it < 4; it++) {
            int i = tid + it * 512;
            int j = i >> 4, c = i & 15;
            *(uint4*)(smp + FW1H + j * 272 + c * 16) = ((const uint4*)g_W1hi)[i];
            *(uint4*)(smp + FW1L + j * 272 + c * 16) = ((const uint4*)g_W1lo)[i];
            int mt = i >> 9, rem = i & 511;
            int j2 = rem >> 3, c2 = rem & 7;
            *(uint4*)(smp + FW2 + mt * 9216 + j2 * 144 + c2 * 16) = ((const uint4*)g_W2i)[i];
        }
        if (tid < 128) { sT[tid] = g_T[tid]; sB1[tid] = g_B1[tid]; sB2[tid] = g_B2[tid]; sLW[tid] = llrW[tid]; sEW[tid] = embW[tid]; }
        if (tid < 64)  { sEW[128 + tid] = embb[tid]; }
    }
    __syncthreads();

    const int pid = tid >> 7;
    const int lt  = tid & 127;
    const int w = lt >> 5, l = lt & 31;
    const int r0 = (w & 1) * 16;
    const int side = w >> 1;
    const int hbar = 1 + pid;
    const float lb0 = llrb[0], lb1 = llrb[1];

    char* ebh_p = smp + pid * EBLK;
    char* ebl_p = ebh_p + 9216;
    const u32 ebh = smb + pid * EBLK;
    const u32 ebl = ebh + 9216;

    const int boff1 = ((l & 7) + ((l >> 1) & 8) + side * 64) * 272 + (l & 8) * 2;
    const int boff2 = ((l & 7) + ((l >> 1) & 8)) * 144 + (l & 8) * 2;
    const u32 w2hiB = smb + FW2 + side * 18432;

    #define HBAR() asm volatile("bar.sync %0, 128;" :: "r"(hbar) : "memory")

    for (int B0 = blockIdx.x * 4 + pid; B0 < NBLK; B0 += 608) {
        const int b = B0 >> 4;
        const int pbase = (B0 & 15) << 6;
        const size_t gpos = (size_t)B0 << 6;

        // ---- entry: compute embedding (stage 0) + fused s=0 head ----
        {
            int r = lt >> 1, hs = lt & 1;
            size_t gp = gpos + r;
            float y0 = yg[gp * 2], y1 = yg[gp * 2 + 1];
            float ev[32];
            float l0 = 0.f, l1 = 0.f, nr = 0.f;
            #pragma unroll
            for (int q = 0; q < 8; q++) {
                int d = hs * 32 + q * 4;
                float4 w0 = *(const float4*)(sEW + d);
                float4 w1 = *(const float4*)(sEW + 64 + d);
                float4 bb = *(const float4*)(sEW + 128 + d);
                float ex = fmaf(y0, w0.x, fmaf(y1, w1.x, bb.x));
                float ey = fmaf(y0, w0.y, fmaf(y1, w1.y, bb.y));
                float ez = fmaf(y0, w0.z, fmaf(y1, w1.z, bb.z));
                float ew = fmaf(y0, w0.w, fmaf(y1, w1.w, bb.w));
                ev[q * 4] = ex; ev[q * 4 + 1] = ey; ev[q * 4 + 2] = ez; ev[q * 4 + 3] = ew;
                float4 wa = *(const float4*)(sLW + d * 2);
                float4 wb = *(const float4*)(sLW + d * 2 + 4);
                l0 += ex * wa.x + ey * wa.z + ez * wb.x + ew * wb.z;
                l1 += ex * wa.y + ey * wa.w + ez * wb.y + ew * wb.w;
                nr += ex * ex + ey * ey + ez * ez + ew * ew;
            }
            #pragma unroll
            for (int q = 0; q < 4; q++) {
                uint4 H, L;
                H.x = pkhi(ev[q*8+0], ev[q*8+1], L.x); H.y = pkhi(ev[q*8+2], ev[q*8+3], L.y);
                H.z = pkhi(ev[q*8+4], ev[q*8+5], L.z); H.w = pkhi(ev[q*8+6], ev[q*8+7], L.w);
                int ad = r * 144 + hs * 64 + q * 16;
                *(uint4*)(ebh_p + ad) = H;
                *(uint4*)(ebl_p + ad) = L;
            }
            l0 += __shfl_xor_sync(0xffffffffu, l0, 1);
            l1 += __shfl_xor_sync(0xffffffffu, l1, 1);
            nr += __shfl_xor_sync(0xffffffffu, nr, 1);
            if (hs == 0) {
                int v = xg[gp];
                sV[pid][1][r] = (unsigned char)v;
                float la = l0 + lb0, lb2 = l1 + lb1;
                float m = fmaxf(la, lb2);
                float x0 = expf(la - m), x1 = expf(lb2 - m);
                float inv = 1.f / (x0 + x1);
                float p0 = x0 * inv, p1 = x1 * inv;
                float pt = v ? p1 : p0;
                float loss = -logf(fminf(fmaxf(pt, 1e-7f), 1.f));
                int p = pbase + r;
                out[(size_t)b * (11 * N_) + p] = loss;
                float2* pr = (float2*)(out + PRED_OFF + (((size_t)(b * N_ + p)) * 11) * 2);
                *pr = make_float2(p0, p1);
                out[NORM_OFF + (size_t)b * (11 * N_) + p] = sqrtf(nr);
            }
        }
        HBAR();

        #pragma unroll 1
        for (int s = 1; s <= 6; s++) {
            const int half = 1 << (s - 1), hm = half - 1;
            const int par = s & 1;

            const int ra = r0 + (l & 15);
            const int sro = ((ra & ~hm) << 1) | (ra & hm);
            float acc1[8][4];
            #pragma unroll
            for (int nt = 0; nt < 8; nt++)
                #pragma unroll
                for (int q = 0; q < 4; q++) acc1[nt][q] = 0.f;

            #pragma unroll
            for (int kc = 0; kc < 8; kc++) {
                int sr = sro + ((kc >= 4) ? half : 0);
                u32 aaddr = (u32)(sr * 144 + ((kc & 3) << 5) + ((l >> 4) << 4));
                u32 ah[4], al[4];
                ldsm4(ebh + aaddr, ah[0], ah[1], ah[2], ah[3]);
                ldsm4(ebl + aaddr, al[0], al[1], al[2], al[3]);
                #pragma unroll
                for (int np = 0; np < 4; np++) {
                    u32 bh[4], bl[4];
                    ldsm4(smb + FW1H + boff1 + np * 4352 + kc * 32, bh[0], bh[1], bh[2], bh[3]);
                    ldsm4(smb + FW1L + boff1 + np * 4352 + kc * 32, bl[0], bl[1], bl[2], bl[3]);
                    #pragma unroll
                    for (int hh = 0; hh < 2; hh++) {
                        float* c = acc1[np * 2 + hh];
                        mma16816(c, ah, bh[2 * hh], bh[2 * hh + 1]);
                        mma16816(c, ah, bl[2 * hh], bl[2 * hh + 1]);
                        mma16816(c, al, bh[2 * hh], bh[2 * hh + 1]);
                    }
                }
            }
            HBAR();

            u32 a2h[4][4], a2l[4][4];
            int ja = r0 + (l >> 2), jb = ja + 8;
            int soa = ((ja & ~hm) << 1) | (ja & hm);
            int sob = ((jb & ~hm) << 1) | (jb & hm);
            {
                int va  = (sV[pid][par][soa] + sV[pid][par][soa + half]) & 1;
                int vbt = (sV[pid][par][sob] + sV[pid][par][sob + half]) & 1;
                #pragma unroll
                for (int nt = 0; nt < 8; nt++) {
                    float* c = acc1[nt];
                    int col = side * 64 + nt * 8 + (l & 3) * 2;
                    float b0 = sB1[col], b1v = sB1[col + 1];
                    float v00 = c[0] + b0, v01 = c[1] + b1v;
                    float v10 = c[2] + b0, v11 = c[3] + b1v;
                    if (side) {
                        int tcol = col - 64;
                        v00 += sT[va * 64 + tcol];  v01 += sT[va * 64 + tcol + 1];
                        v10 += sT[vbt * 64 + tcol]; v11 += sT[vbt * 64 + tcol + 1];
                    }
                    v00 = fmaxf(v00, 0.f); v01 = fmaxf(v01, 0.f);
                    v10 = fmaxf(v10, 0.f); v11 = fmaxf(v11, 0.f);
                    int kc2 = nt >> 1, qq = (nt & 1) * 2;
                    a2h[kc2][qq]     = pkhi(v00, v01, a2l[kc2][qq]);
                    a2h[kc2][qq + 1] = pkhi(v10, v11, a2l[kc2][qq + 1]);
                }
            }

            float acc2[8][4];
            #pragma unroll
            for (int nt = 0; nt < 8; nt++)
                #pragma unroll
                for (int q = 0; q < 4; q++) acc2[nt][q] = 0.f;

            #pragma unroll
            for (int kc = 0; kc < 4; kc++) {
                #pragma unroll
                for (int np = 0; np < 4; np++) {
                    u32 bh[4], bl[4];
                    ldsm4(w2hiB + boff2 + np * 2304 + kc * 32, bh[0], bh[1], bh[2], bh[3]);
                    ldsm4(w2hiB + 9216 + boff2 + np * 2304 + kc * 32, bl[0], bl[1], bl[2], bl[3]);
                    #pragma unroll
                    for (int hh = 0; hh < 2; hh++) {
                        float* c = acc2[np * 2 + hh];
                        mma16816(c, a2h[kc], bh[2 * hh], bh[2 * hh + 1]);
                        mma16816(c, a2h[kc], bl[2 * hh], bl[2 * hh + 1]);
                        mma16816(c, a2l[kc], bh[2 * hh], bh[2 * hh + 1]);
                    }
                }
            }

            {
                int pra = (ja << 1) | side;
                int prb = (jb << 1) | side;
                float L0[2] = {0.f, 0.f}, L1[2] = {0.f, 0.f}, NR[2] = {0.f, 0.f};
                size_t pa64 = ((size_t)b * N_ + pbase + pra) * 64;
                size_t pb64 = ((size_t)b * N_ + pbase + prb) * 64;
                #pragma unroll
                for (int nt = 0; nt < 8; nt++) {
                    float* c = acc2[nt];
                    int col = nt * 8 + (l & 3) * 2;
                    float b0 = sB2[side * 64 + col], b1v = sB2[side * 64 + col + 1];
                    float o00 = c[0] + b0, o01 = c[1] + b1v;
                    float o10 = c[2] + b0, o11 = c[3] + b1v;
                    u32 lo0, lo1;
                    u32 hi0 = pkhi(o00, o01, lo0);
                    u32 hi1 = pkhi(o10, o11, lo1);
                    if (s < 6) {
                        *(u32*)(ebh_p + pra * 144 + col * 2) = hi0;
                        *(u32*)(ebl_p + pra * 144 + col * 2) = lo0;
                        *(u32*)(ebh_p + prb * 144 + col * 2) = hi1;
                        *(u32*)(ebl_p + prb * 144 + col * 2) = lo1;
                    } else {
                        *(u32*)(&g_pln_h[0][pa64 + col]) = hi0;
                        *(u32*)(&g_pln_l[0][pa64 + col]) = lo0;
                        *(u32*)(&g_pln_h[0][pb64 + col]) = hi1;
                        *(u32*)(&g_pln_l[0][pb64 + col]) = lo1;
                    }
                    float w0 = sLW[col * 2], w1 = sLW[col * 2 + 1];
                    float w2 = sLW[col * 2 + 2], w3 = sLW[col * 2 + 3];
                    L0[0] += o00 * w0 + o01 * w2;
                    L1[0] += o00 * w1 + o01 * w3;
                    NR[0] += o00 * o00 + o01 * o01;
                    L0[1] += o10 * w0 + o11 * w2;
                    L1[1] += o10 * w1 + o11 * w3;
                    NR[1] += o10 * o10 + o11 * o11;
                }
                #pragma unroll
                for (int off = 2; off >= 1; off >>= 1) {
                    #pragma unroll
                    for (int hh = 0; hh < 2; hh++) {
                        L0[hh] += __shfl_xor_sync(0xffffffffu, L0[hh], off);
                        L1[hh] += __shfl_xor_sync(0xffffffffu, L1[hh], off);
                        NR[hh] += __shfl_xor_sync(0xffffffffu, NR[hh], off);
                    }
                }
                if ((l & 3) == 0) {
                    #pragma unroll
                    for (int hh = 0; hh < 2; hh++) {
                        int jj = hh ? jb : ja;
                        int so = hh ? sob : soa;
                        int pr = (jj << 1) | side;
                        unsigned char vxb = (unsigned char)((sV[pid][par][so] + sV[pid][par][so + half]) & 1);
                        unsigned char veb = sV[pid][par][so + half];
                        unsigned char vp = side ? veb : vxb;
                        if (s < 6) sV[pid][par ^ 1][pr] = vp;
                        else       g_v[0][(size_t)b * N_ + pbase + pr] = vp;
                        int p = pbase + pr;
                        float l0 = L0[hh] + lb0, l1 = L1[hh] + lb1;
                        float mm = fmaxf(l0, l1);
                        float x0 = expf(l0 - mm), x1 = expf(l1 - mm);
                        float inv = 1.f / (x0 + x1);
                        float p0 = x0 * inv, p1 = x1 * inv;
                        float pt = vp ? p1 : p0;
                        float loss = -logf(fminf(fmaxf(pt, 1e-7f), 1.f));
                        out[(size_t)b * (11 * N_) + (size_t)s * N_ + p] = loss;
                        float2* pr2 = (float2*)(out + PRED_OFF + (((size_t)(b * N_ + p)) * 11 + s) * 2);
                        *pr2 = make_float2(p0, p1);
                        out[NORM_OFF + (size_t)b * (11 * N_) + (size_t)s * N_ + p] = sqrtf(NR[hh]);
                    }
                }
            }
            HBAR();
        }
    }
    #undef HBAR
}

// ---------------- fused late pair (sA, sA+1), sA in {7, 9}; planes in/out ----------------
__global__ void __launch_bounds__(512, 1)
fusedlate_kernel(int sA, int src, int dostore,
                 const float* __restrict__ llrW, const float* __restrict__ llrb,
                 float* __restrict__ out) {
    extern __shared__ char smp[];
    const u32 smb = smem_u32(smp);
    float* sT  = (float*)(smp + FT);
    float* sB1 = (float*)(smp + FB1);
    float* sB2 = (float*)(smp + FB2);
    float* sLW = (float*)(smp + FLW);
    __shared__ unsigned char sV[4][2][64];

    const int tid = threadIdx.x;
    {
        #pragma unroll
        for (int it = 0; it < 4; it++) {
            int i = tid + it * 512;
            int j = i >> 4, c = i & 15;
            *(uint4*)(smp + FW1H + j * 272 + c * 16) = ((const uint4*)g_W1hi)[i];
            *(uint4*)(smp + FW1L + j * 272 + c * 16) = ((const uint4*)g_W1lo)[i];
            int mt = i >> 9, rem = i & 511;
            int j2 = rem >> 3, c2 = rem & 7;
            *(uint4*)(smp + FW2 + mt * 9216 + j2 * 144 + c2 * 16) = ((const uint4*)g_W2i)[i];
        }
        if (tid < 128) { sT[tid] = g_T[tid]; sB1[tid] = g_B1[tid]; sB2[tid] = g_B2[tid]; sLW[tid] = llrW[tid]; }
    }
    __syncthreads();

    const int pid = tid >> 7;
    const int lt  = tid & 127;
    const int w = lt >> 5, l = lt & 31;
    const int r0 = (w & 1) * 16;
    const int side = w >> 1;
    const int hbar = 1 + pid;
    const int dst = src ^ 1;
    const int halfA = 1 << (sA - 1);
    const float lb0 = llrb[0], lb1 = llrb[1];

    char* ebh_p = smp + pid * EBLK;
    char* ebl_p = ebh_p + 9216;
    const u32 ebh = smb + pid * EBLK;
    const u32 ebl = ebh + 9216;

    const int boff1 = ((l & 7) + ((l >> 1) & 8) + side * 64) * 272 + (l & 8) * 2;
    const int boff2 = ((l & 7) + ((l >> 1) & 8)) * 144 + (l & 8) * 2;
    const u32 w2hiB = smb + FW2 + side * 18432;

    const __nv_bfloat16* sph = g_pln_h[src];
    const __nv_bfloat16* spl = g_pln_l[src];

    #define HBAR() asm volatile("bar.sync %0, 128;" :: "r"(hbar) : "memory")
    #define GIMAP(RI) (hbase + ((RI) >> 5) * (halfA << 1) + ((((RI) >> 4) & 1)) * halfA + (m0 >> 1) + ((RI) & 15))

    for (int T = blockIdx.x * 4 + pid; T < NBLK; T += 608) {
        const int b = T >> 4;
        const int tau = T & 15;
        const int h = tau >> (sA - 5);
        const int hbase = h << (sA + 1);
        const int m0 = (tau & ((1 << (sA - 5)) - 1)) << 5;
        const unsigned char* vbg = g_v[src] + (size_t)b * N_;

        // ---- entry: copy bf16 hi/lo rows (butterfly-gathered), plus bits ----
        #pragma unroll
        for (int it = 0; it < 8; it++) {
            int c = lt + (it << 7);          // 0..1023
            int pl = c >> 9, rem = c & 511;
            int r = rem >> 3, f8 = rem & 7;
            int gi = GIMAP(r);
            const __nv_bfloat16* srcp = (pl ? spl : sph) + ((size_t)b * N_ + gi) * 64 + (f8 << 3);
            *(uint4*)((pl ? ebl_p : ebh_p) + r * 144 + f8 * 16) = *(const uint4*)srcp;
        }
        if (lt < 64) sV[pid][0][lt] = vbg[GIMAP(lt)];
        HBAR();

        #pragma unroll
        for (int it2 = 0; it2 < 2; it2++) {
            const int half = 16 << it2, hm = half - 1;
            const int s = sA + it2;

            const int ra = r0 + (l & 15);
            const int sro = ((ra & ~hm) << 1) | (ra & hm);
            float acc1[8][4];
            #pragma unroll
            for (int nt = 0; nt < 8; nt++)
                #pragma unroll
                for (int q = 0; q < 4; q++) acc1[nt][q] = 0.f;

            #pragma unroll
            for (int kc = 0; kc < 8; kc++) {
                int sr = sro + ((kc >= 4) ? half : 0);
                u32 aaddr = (u32)(sr * 144 + ((kc & 3) << 5) + ((l >> 4) << 4));
                u32 ah[4], al[4];
                ldsm4(ebh + aaddr, ah[0], ah[1], ah[2], ah[3]);
                ldsm4(ebl + aaddr, al[0], al[1], al[2], al[3]);
                #pragma unroll
                for (int np = 0; np < 4; np++) {
                    u32 bh[4], bl[4];
                    ldsm4(smb + FW1H + boff1 + np * 4352 + kc * 32, bh[0], bh[1], bh[2], bh[3]);
                    ldsm4(smb + FW1L + boff1 + np * 4352 + kc * 32, bl[0], bl[1], bl[2], bl[3]);
                    #pragma unroll
                    for (int hh = 0; hh < 2; hh++) {
                        float* c = acc1[np * 2 + hh];
                        mma16816(c, ah, bh[2 * hh], bh[2 * hh + 1]);
                        mma16816(c, ah, bl[2 * hh], bl[2 * hh + 1]);
                        mma16816(c, al, bh[2 * hh], bh[2 * hh + 1]);
                    }
                }
            }
            HBAR();

            u32 a2h[4][4], a2l[4][4];
            int ja = r0 + (l >> 2), jb = ja + 8;
            int soa = ((ja & ~hm) << 1) | (ja & hm);
            int sob = ((jb & ~hm) << 1) | (jb & hm);
            {
                int va  = (sV[pid][it2][soa] + sV[pid][it2][soa + half]) & 1;
                int vbt = (sV[pid][it2][sob] + sV[pid][it2][sob + half]) & 1;
                #pragma unroll
                for (int nt = 0; nt < 8; nt++) {
                    float* c = acc1[nt];
                    int col = side * 64 + nt * 8 + (l & 3) * 2;
                    float b0 = sB1[col], b1v = sB1[col + 1];
                    float v00 = c[0] + b0, v01 = c[1] + b1v;
                    float v10 = c[2] + b0, v11 = c[3] + b1v;
                    if (side) {
                        int tcol = col - 64;
                        v00 += sT[va * 64 + tcol];  v01 += sT[va * 64 + tcol + 1];
                        v10 += sT[vbt * 64 + tcol]; v11 += sT[vbt * 64 + tcol + 1];
                    }
                    v00 = fmaxf(v00, 0.f); v01 = fmaxf(v01, 0.f);
                    v10 = fmaxf(v10, 0.f); v11 = fmaxf(v11, 0.f);
                    int kc2 = nt >> 1, qq = (nt & 1) * 2;
                    a2h[kc2][qq]     = pkhi(v00, v01, a2l[kc2][qq]);
                    a2h[kc2][qq + 1] = pkhi(v10, v11, a2l[kc2][qq + 1]);
                }
            }

            float acc2[8][4];
            #pragma unroll
            for (int nt = 0; nt < 8; nt++)
                #pragma unroll
                for (int q = 0; q < 4; q++) acc2[nt][q] = 0.f;

            #pragma unroll
            for (int kc = 0; kc < 4; kc++) {
                #pragma unroll
                for (int np = 0; np < 4; np++) {
                    u32 bh[4], bl[4];
                    ldsm4(w2hiB + boff2 + np * 2304 + kc * 32, bh[0], bh[1], bh[2], bh[3]);
                    ldsm4(w2hiB + 9216 + boff2 + np * 2304 + kc * 32, bl[0], bl[1], bl[2], bl[3]);
                    #pragma unroll
                    for (int hh = 0; hh < 2; hh++) {
                        float* c = acc2[np * 2 + hh];
                        mma16816(c, a2h[kc], bh[2 * hh], bh[2 * hh + 1]);
                        mma16816(c, a2h[kc], bl[2 * hh], bl[2 * hh + 1]);
                        mma16816(c, a2l[kc], bh[2 * hh], bh[2 * hh + 1]);
                    }
                }
            }

            {
                int pra = (ja << 1) | side;
                int prb = (jb << 1) | side;
                int gpa, gpb;
                if (it2 == 0) {
                    gpa = hbase + ((pra >> 5) << sA) + m0 + (pra & 31);
                    gpb = hbase + ((prb >> 5) << sA) + m0 + (prb & 31);
                } else {
                    gpa = hbase + (m0 << 1) + pra;
                    gpb = hbase + (m0 << 1) + prb;
                }
                float L0[2] = {0.f, 0.f}, L1[2] = {0.f, 0.f}, NR[2] = {0.f, 0.f};
                size_t ga64 = ((size_t)b * N_ + gpa) * 64;
                size_t gb64 = ((size_t)b * N_ + gpb) * 64;
                #pragma unroll
                for (int nt = 0; nt < 8; nt++) {
                    float* c = acc2[nt];
                    int col = nt * 8 + (l & 3) * 2;
                    float b0 = sB2[side * 64 + col], b1v = sB2[side * 64 + col + 1];
                    float o00 = c[0] + b0, o01 = c[1] + b1v;
                    float o10 = c[2] + b0, o11 = c[3] + b1v;
                    if (it2 == 0) {
                        u32 lo0, lo1;
                        u32 hi0 = pkhi(o00, o01, lo0);
                        u32 hi1 = pkhi(o10, o11, lo1);
                        *(u32*)(ebh_p + pra * 144 + col * 2) = hi0;
                        *(u32*)(ebl_p + pra * 144 + col * 2) = lo0;
                        *(u32*)(ebh_p + prb * 144 + col * 2) = hi1;
                        *(u32*)(ebl_p + prb * 144 + col * 2) = lo1;
                    } else if (dostore) {
                        u32 lo0, lo1;
                        u32 hi0 = pkhi(o00, o01, lo0);
                        u32 hi1 = pkhi(o10, o11, lo1);
                        *(u32*)(&g_pln_h[dst][ga64 + col]) = hi0;
                        *(u32*)(&g_pln_l[dst][ga64 + col]) = lo0;
                        *(u32*)(&g_pln_h[dst][gb64 + col]) = hi1;
                        *(u32*)(&g_pln_l[dst][gb64 + col]) = lo1;
                    }
                    float w0 = sLW[col * 2], w1 = sLW[col * 2 + 1];
                    float w2 = sLW[col * 2 + 2], w3 = sLW[col * 2 + 3];
                    L0[0] += o00 * w0 + o01 * w2;
                    L1[0] += o00 * w1 + o01 * w3;
                    NR[0] += o00 * o00 + o01 * o01;
                    L0[1] += o10 * w0 + o11 * w2;
                    L1[1] += o10 * w1 + o11 * w3;
                    NR[1] += o10 * o10 + o11 * o11;
                }
                #pragma unroll
                for (int off = 2; off >= 1; off >>= 1) {
                    #pragma unroll
                    for (int hh = 0; hh < 2; hh++) {
                        L0[hh] += __shfl_xor_sync(0xffffffffu, L0[hh], off);
                        L1[hh] += __shfl_xor_sync(0xffffffffu, L1[hh], off);
                        NR[hh] += __shfl_xor_sync(0xffffffffu, NR[hh], off);
                    }
                }
                if ((l & 3) == 0) {
                    #pragma unroll
                    for (int hh = 0; hh < 2; hh++) {
                        int jj = hh ? jb : ja;
                        int so = hh ? sob : soa;
                        int pr = (jj << 1) | side;
                        int gp = hh ? gpb : gpa;
                        unsigned char vxb = (unsigned char)((sV[pid][it2][so] + sV[pid][it2][so + half]) & 1);
                        unsigned char veb = sV[pid][it2][so + half];
                        unsigned char vp = side ? veb : vxb;
                        if (it2 == 0)      sV[pid][1][pr] = vp;
                        else if (dostore)  g_v[dst][(size_t)b * N_ + gp] = vp;
                        float l0 = L0[hh] + lb0, l1 = L1[hh] + lb1;
                        float mm = fmaxf(l0, l1);
                        float x0 = expf(l0 - mm), x1 = expf(l1 - mm);
                        float inv = 1.f / (x0 + x1);
                        float p0 = x0 * inv, p1 = x1 * inv;
                        float pt = vp ? p1 : p0;
                        float loss = -logf(fminf(fmaxf(pt, 1e-7f), 1.f));
                        out[(size_t)b * (11 * N_) + (size_t)s * N_ + gp] = loss;
                        float2* pr2 = (float2*)(out + PRED_OFF + (((size_t)(b * N_ + gp)) * 11 + s) * 2);
                        *pr2 = make_float2(p0, p1);
                        out[NORM_OFF + (size_t)b * (11 * N_) + (size_t)s * N_ + gp] = sqrtf(NR[hh]);
                    }
                }
            }
            HBAR();
        }
    }
    #undef HBAR
    #undef GIMAP
}

// ---------------- launch ----------------
extern "C" void kernel_launch(void* const* d_in, const int* in_sizes, int n_in,
                              void* d_out, int out_size) {
    const int*   x    = (const int*)d_in[0];
    const float* y    = (const float*)d_in[1];
    const float* embW = (const float*)d_in[2];
    const float* embb = (const float*)d_in[3];
    const float* lab  = (const float*)d_in[4];
    const float* cnW1 = (const float*)d_in[5];
    const float* cnb1 = (const float*)d_in[6];
    const float* cnW2 = (const float*)d_in[7];
    const float* cnb2 = (const float*)d_in[8];
    const float* bnW1 = (const float*)d_in[9];
    const float* bnb1 = (const float*)d_in[10];
    const float* bnW2 = (const float*)d_in[11];
    const float* bnb2 = (const float*)d_in[12];
    const float* llrW = (const float*)d_in[13];
    const float* llrb = (const float*)d_in[14];
    float* out = (float*)d_out;

    cudaFuncSetAttribute(fused16_kernel, cudaFuncAttributeMaxDynamicSharedMemorySize, DSMEM_FUSED);
    cudaFuncSetAttribute(fusedlate_kernel, cudaFuncAttributeMaxDynamicSharedMemorySize, DSMEM_FUSED);

    prep_kernel<<<1, 256>>>(cnW1, bnW1, cnW2, bnW2, cnb1, bnb1, cnb2, bnb2, lab);
    fused16_kernel<<<152, 512, DSMEM_FUSED>>>(x, y, embW, embb, llrW, llrb, out);
    fusedlate_kernel<<<152, 512, DSMEM_FUSED>>>(7, 0, 1, llrW, llrb, out);   // stages 7+8
    fusedlate_kernel<<<152, 512, DSMEM_FUSED>>>(9, 1, 0, llrW, llrb, out);   // stages 9+10
}